// round 1
// baseline (speedup 1.0000x reference)
#include <cuda_runtime.h>
#include <math.h>
#include <stdint.h>

// ---------------- problem constants ----------------
#define NB    8          // batch
#define NPART 32         // NB * TOPN
#define NANCH 1614
#define CAT   200

// output layout (float32, 9664 elems):
// [0,1600)      raw_logits (8,200)
// [1600,3200)   concat_logits (8,200)
// [3200,9600)   part_logits (8,4,200)
// [9600,9632)   top_n_idx as float (8,4)
// [9632,9664)   top_n_prob (8,4)

// ---------------- scratch (device globals; no allocations) ----------------
__device__ float g_F8 [NB    * 2048 * 196];        // stem features, main imgs
__device__ float g_Fp [NPART * 2048 * 196];        // stem features, part imgs
__device__ float g_part[NPART * 3 * 448 * 448];    // cropped part images
__device__ float g_ps [9 * NB * 128 * 196];        // split-K partials (reused)
__device__ float g_d1 [NB * 128 * 196];
__device__ float g_d2 [NB * 128 * 49];
__device__ float g_d3 [NB * 128 * 16];
__device__ float g_g8 [NB * 2048];
__device__ float g_gp [NPART * 2048];
__device__ float g_rpn[NB * NANCH];
__device__ int   g_boxes[NANCH * 4];
__device__ float g_area [NANCH];
__device__ int   g_topidx[NB * 4];

// ---------------- anchor boxes (replicates numpy generation) ----------------
__global__ void boxes_k()
{
    int a = blockIdx.x * blockDim.x + threadIdx.x;
    if (a >= NANCH) return;
    double CB1 = pow(2.0, 1.0 / 3.0);
    double CB2 = pow(2.0, 2.0 / 3.0);
    int stride, size, ow;
    int scale_i, ar_i, cell;
    double s;
    if (a < 1176) {            // stride 32, size 48, 14x14, scales {CB1,CB2}
        stride = 32; size = 48; ow = 14;
        int w = a; scale_i = w / (3 * 196); int r = w % (3 * 196);
        ar_i = r / 196; cell = r % 196;
        s = (scale_i == 0) ? CB1 : CB2;
    } else if (a < 1470) {     // stride 64, size 96, 7x7
        stride = 64; size = 96; ow = 7;
        int w = a - 1176; scale_i = w / (3 * 49); int r = w % (3 * 49);
        ar_i = r / 49; cell = r % 49;
        s = (scale_i == 0) ? CB1 : CB2;
    } else {                   // stride 128, size 192, 4x4, scales {1,CB1,CB2}
        stride = 128; size = 192; ow = 4;
        int w = a - 1470; scale_i = w / (3 * 16); int r = w % (3 * 16);
        ar_i = r / 16; cell = r % 16;
        s = (scale_i == 0) ? 1.0 : ((scale_i == 1) ? CB1 : CB2);
    }
    double ar = (ar_i == 0) ? 0.667 : ((ar_i == 1) ? 1.0 : 1.5);
    int cyi = cell / ow, cxi = cell % ow;
    double cy = (double)cyi * stride + stride * 0.5;
    double cx = (double)cxi * stride + stride * 0.5;
    double sq = sqrt(ar);
    double hh = size * s / sq;
    double ww = size * s * sq;
    int y0 = (int)(cy - hh * 0.5 + 224.0);
    int x0 = (int)(cx - ww * 0.5 + 224.0);
    int y1 = (int)(cy + hh * 0.5 + 224.0);
    int x1 = (int)(cx + ww * 0.5 + 224.0);
    g_boxes[a * 4 + 0] = y0;
    g_boxes[a * 4 + 1] = x0;
    g_boxes[a * 4 + 2] = y1;
    g_boxes[a * 4 + 3] = x1;
    g_area[a] = (float)(y1 - y0) * (float)(x1 - x0);
}

// ---------------- implicit-GEMM direct conv ----------------
// OUT[img][m][col] = (relu)(bias[m] + sum_k W[m][k] * patch(img,k,col))
// k = ci*KH*KW + ky*KW + kx ; col = oy*WOUT + ox
// Tile: 64(M) x 64(N) x 8(K), 256 threads, 4x4 per-thread register tile.
template<int CIN,int KH,int KW,int STRIDE,int PAD,int HIN,int WIN,int HOUT,int WOUT,int RELU,int SPLIT>
__global__ __launch_bounds__(256)
void conv_gemm(const float* __restrict__ IN, const float* __restrict__ W,
               const float* __restrict__ bias, float* __restrict__ OUT,
               int M, int NIMG)
{
    constexpr int KHW  = KH * KW;
    constexpr int KTOT = CIN * KHW;
    constexpr int KS   = (KTOT + SPLIT - 1) / SPLIT;
    constexpr int NCOL = HOUT * WOUT;

    const int img = blockIdx.z / SPLIT;
    const int sp  = blockIdx.z % SPLIT;
    const int kbeg = sp * KS;
    const int kend = (kbeg + KS < KTOT) ? (kbeg + KS) : KTOT;
    const int m0 = blockIdx.x * 64;
    const int n0 = blockIdx.y * 64;

    __shared__ __align__(16) float As[8][64];
    __shared__ __align__(16) float Bs[8][64];

    float acc[4][4];
#pragma unroll
    for (int i = 0; i < 4; i++)
#pragma unroll
        for (int j = 0; j < 4; j++) acc[i][j] = 0.f;

    const int tid = threadIdx.x;
    const int a_m = tid >> 2;            // 0..63
    const int a_k = (tid & 3) << 1;      // 0,2,4,6
    const int b_k = tid >> 5;            // 0..7
    const int b_n = tid & 31;            // 0..31
    const int tr  = tid >> 4;            // 0..15
    const int tc  = tid & 15;            // 0..15

    const float* IMGP = IN + (size_t)img * CIN * HIN * WIN;

    for (int k0 = kbeg; k0 < kend; k0 += 8) {
        // load A tile (weights)
        {
            const float* wrow = W + (size_t)(m0 + a_m) * KTOT;
            int k = k0 + a_k;
            As[a_k    ][a_m] = (k     < kend) ? wrow[k]     : 0.f;
            As[a_k + 1][a_m] = (k + 1 < kend) ? wrow[k + 1] : 0.f;
        }
        // load B tile (implicit im2col gather)
        {
            int k = k0 + b_k;
            bool kok = (k < kend);
            int ci = 0, ky = 0, kx = 0;
            if (kok) {
                ci = k / KHW;
                int r = k - ci * KHW;
                ky = r / KW;
                kx = r - ky * KW;
            }
#pragma unroll
            for (int h = 0; h < 2; h++) {
                int nn  = b_n + 32 * h;
                int col = n0 + nn;
                float v = 0.f;
                if (kok && col < NCOL) {
                    int oy = col / WOUT;
                    int ox = col - oy * WOUT;
                    int iy = oy * STRIDE - PAD + ky;
                    int ix = ox * STRIDE - PAD + kx;
                    if (iy >= 0 && iy < HIN && ix >= 0 && ix < WIN)
                        v = __ldg(&IMGP[(size_t)ci * (HIN * WIN) + iy * WIN + ix]);
                }
                Bs[b_k][nn] = v;
            }
        }
        __syncthreads();
#pragma unroll
        for (int kk = 0; kk < 8; kk++) {
            float4 a = *reinterpret_cast<const float4*>(&As[kk][tr << 2]);
            float4 b = *reinterpret_cast<const float4*>(&Bs[kk][tc << 2]);
            acc[0][0] += a.x * b.x; acc[0][1] += a.x * b.y; acc[0][2] += a.x * b.z; acc[0][3] += a.x * b.w;
            acc[1][0] += a.y * b.x; acc[1][1] += a.y * b.y; acc[1][2] += a.y * b.z; acc[1][3] += a.y * b.w;
            acc[2][0] += a.z * b.x; acc[2][1] += a.z * b.y; acc[2][2] += a.z * b.z; acc[2][3] += a.z * b.w;
            acc[3][0] += a.w * b.x; acc[3][1] += a.w * b.y; acc[3][2] += a.w * b.z; acc[3][3] += a.w * b.w;
        }
        __syncthreads();
    }

#pragma unroll
    for (int i = 0; i < 4; i++) {
        int gm = m0 + (tr << 2) + i;
#pragma unroll
        for (int j = 0; j < 4; j++) {
            int col = n0 + (tc << 2) + j;
            if (col < NCOL) {
                if (SPLIT == 1) {
                    float v = acc[i][j] + bias[gm];
                    if (RELU) v = fmaxf(v, 0.f);
                    OUT[((size_t)img * M + gm) * NCOL + col] = v;
                } else {
                    OUT[(((size_t)sp * NIMG + img) * M + gm) * NCOL + col] = acc[i][j];
                }
            }
        }
    }
}

// sum split-K partials + bias + relu
__global__ void reduce_br(float* __restrict__ out, const float* __restrict__ part,
                          const float* __restrict__ bias, int nimg, int M, int ncol, int split)
{
    int idx = blockIdx.x * blockDim.x + threadIdx.x;
    int tot = nimg * M * ncol;
    if (idx >= tot) return;
    int m = (idx / ncol) % M;
    float s = 0.f;
    for (int sp = 0; sp < split; sp++) s += part[(size_t)sp * tot + idx];
    out[idx] = fmaxf(s + bias[m], 0.f);
}

// spatial mean: one warp per (img, channel)
__global__ void mean_k(const float* __restrict__ F, float* __restrict__ G, int ncol)
{
    int img  = blockIdx.x;
    int oc   = blockIdx.y * 8 + (threadIdx.x >> 5);
    int lane = threadIdx.x & 31;
    const float* row = F + ((size_t)img * 2048 + oc) * ncol;
    float s = 0.f;
    for (int j = lane; j < ncol; j += 32) s += row[j];
#pragma unroll
    for (int o = 16; o; o >>= 1) s += __shfl_xor_sync(0xffffffffu, s, o);
    if (lane == 0) G[(size_t)img * 2048 + oc] = s / (float)ncol;
}

// generic FC: out[row*200+cls] = bias[cls] + dot(G[row], W[cls]); warp per class
__global__ void fc_k(const float* __restrict__ G, const float* __restrict__ Wt,
                     const float* __restrict__ b, float* __restrict__ out, int K)
{
    int row  = blockIdx.x;
    int cls  = blockIdx.y * 4 + (threadIdx.x >> 5);
    int lane = threadIdx.x & 31;
    const float* g = G  + (size_t)row * K;
    const float* w = Wt + (size_t)cls * K;
    float s = 0.f;
    for (int k = lane; k < K; k += 32) s += g[k] * w[k];
#pragma unroll
    for (int o = 16; o; o >>= 1) s += __shfl_xor_sync(0xffffffffu, s, o);
    if (lane == 0) out[row * CAT + cls] = s + b[cls];
}

// concat_logits: features = [part_feat(4x2048 of this image), global_feat(2048)]
__global__ void fc_concat_k(const float* __restrict__ GP, const float* __restrict__ G8,
                            const float* __restrict__ Wt, const float* __restrict__ b,
                            float* __restrict__ out)
{
    int bimg = blockIdx.x;
    int cls  = blockIdx.y * 4 + (threadIdx.x >> 5);
    int lane = threadIdx.x & 31;
    const float* w = Wt + (size_t)cls * 10240;
    float s = 0.f;
    for (int k = lane; k < 10240; k += 32) {
        float f = (k < 8192)
            ? GP[(size_t)(bimg * 4 + (k >> 11)) * 2048 + (k & 2047)]
            : G8[(size_t)bimg * 2048 + (k - 8192)];
        s += f * w[k];
    }
#pragma unroll
    for (int o = 16; o; o >>= 1) s += __shfl_xor_sync(0xffffffffu, s, o);
    if (lane == 0) out[bimg * CAT + cls] = s + b[cls];
}

// tidy 1x1 convs -> rpn scores, matching reshape/concat layout
__global__ void rpn_k(const float* __restrict__ d1, const float* __restrict__ d2,
                      const float* __restrict__ d3,
                      const float* __restrict__ w1, const float* __restrict__ b1,
                      const float* __restrict__ w2, const float* __restrict__ b2,
                      const float* __restrict__ w3, const float* __restrict__ b3,
                      float* __restrict__ rpn)
{
    int img = blockIdx.x;
    for (int j = threadIdx.x; j < NANCH; j += blockDim.x) {
        float s;
        if (j < 1176) {
            int ch = j / 196, pos = j % 196;
            const float* in = d1 + (size_t)img * 128 * 196 + pos;
            const float* w  = w1 + ch * 128;
            s = b1[ch];
            for (int c = 0; c < 128; c++) s += in[c * 196] * w[c];
        } else if (j < 1470) {
            int jj = j - 1176;
            int ch = jj / 49, pos = jj % 49;
            const float* in = d2 + (size_t)img * 128 * 49 + pos;
            const float* w  = w2 + ch * 128;
            s = b2[ch];
            for (int c = 0; c < 128; c++) s += in[c * 49] * w[c];
        } else {
            int jj = j - 1470;
            int ch = jj / 16, pos = jj % 16;
            const float* in = d3 + (size_t)img * 128 * 16 + pos;
            const float* w  = w3 + ch * 128;
            s = b3[ch];
            for (int c = 0; c < 128; c++) s += in[c * 16] * w[c];
        }
        rpn[img * NANCH + j] = s;
    }
}

// NMS: pick top-4 with IoU suppression (first-index tie-break like jnp.argmax)
__global__ void nms_k(const float* __restrict__ rpn,
                      float* __restrict__ out_idx_f, float* __restrict__ out_prob)
{
    int img = blockIdx.x;
    __shared__ float sc[NANCH];
    __shared__ unsigned char valid[NANCH];
    __shared__ float rv[256];
    __shared__ int   ri[256];
    __shared__ float pb[5];   // y0,x0,y1,x1,area of pick
    int tid = threadIdx.x;
    for (int j = tid; j < NANCH; j += 256) {
        sc[j] = rpn[img * NANCH + j];
        valid[j] = 1;
    }
    __syncthreads();
    for (int t = 0; t < 4; t++) {
        float bv = -INFINITY;
        int   bi = 0x7fffffff;
        for (int j = tid; j < NANCH; j += 256) {
            if (valid[j]) {
                float v = sc[j];
                if (v > bv || (v == bv && j < bi)) { bv = v; bi = j; }
            }
        }
        rv[tid] = bv; ri[tid] = bi;
        __syncthreads();
        for (int o = 128; o; o >>= 1) {
            if (tid < o) {
                float v2 = rv[tid + o]; int i2 = ri[tid + o];
                if (v2 > rv[tid] || (v2 == rv[tid] && i2 < ri[tid])) { rv[tid] = v2; ri[tid] = i2; }
            }
            __syncthreads();
        }
        if (tid == 0) {
            int p = ri[0];
            g_topidx[img * 4 + t] = p;
            out_idx_f[img * 4 + t] = (float)p;
            out_prob [img * 4 + t] = sc[p];
            pb[0] = (float)g_boxes[p * 4 + 0];
            pb[1] = (float)g_boxes[p * 4 + 1];
            pb[2] = (float)g_boxes[p * 4 + 2];
            pb[3] = (float)g_boxes[p * 4 + 3];
            pb[4] = g_area[p];
        }
        __syncthreads();
        float by0 = pb[0], bx0 = pb[1], by1 = pb[2], bx1 = pb[3], ba = pb[4];
        for (int j = tid; j < NANCH; j += 256) {
            if (!valid[j]) continue;
            float ty = fmaxf((float)g_boxes[j * 4 + 0], by0);
            float tx = fmaxf((float)g_boxes[j * 4 + 1], bx0);
            float cy = fminf((float)g_boxes[j * 4 + 2], by1);
            float cx = fminf((float)g_boxes[j * 4 + 3], bx1);
            float wh0 = cy - ty, wh1 = cx - tx;
            float inter = (wh0 < 0.f || wh1 < 0.f) ? 0.f : wh0 * wh1;
            float iou = inter / (g_area[j] + ba - inter);
            if (!(iou < 0.25f)) valid[j] = 0;
        }
        __syncthreads();
    }
}

// crop-resize top boxes from (implicitly zero-padded) x into part images
__global__ void crop_k(const float* __restrict__ x)
{
    int p = blockIdx.x;     // part 0..31
    int i = blockIdx.y;     // output row 0..447
    int j = threadIdx.x;    // output col 0..447
    int b = p >> 2;
    int bi = g_topidx[p];
    int y0 = g_boxes[bi * 4 + 0], x0 = g_boxes[bi * 4 + 1];
    int y1 = g_boxes[bi * 4 + 2], x1 = g_boxes[bi * 4 + 3];
    if (y1 < y0 + 1) y1 = y0 + 1;
    if (x1 < x0 + 1) x1 = x0 + 1;
    float stepy = __fdiv_rn((float)(y1 - 1 - y0), 447.f);
    float stepx = __fdiv_rn((float)(x1 - 1 - x0), 447.f);
    float fy = __fadd_rn((float)y0, __fmul_rn((float)i, stepy));
    float fx = __fadd_rn((float)x0, __fmul_rn((float)j, stepx));
    int yl = (int)floorf(fy);
    int xl = (int)floorf(fx);
    int yh = yl + 1; if (yh > y1 - 1) yh = y1 - 1;
    int xh = xl + 1; if (xh > x1 - 1) xh = x1 - 1;
    float wy = fy - (float)yl;
    float wx = fx - (float)xl;
    int ylo = yl - 224, yho = yh - 224, xlo = xl - 224, xho = xh - 224;
    bool ylv = (ylo >= 0 && ylo < 448), yhv = (yho >= 0 && yho < 448);
    bool xlv = (xlo >= 0 && xlo < 448), xhv = (xho >= 0 && xho < 448);
#pragma unroll
    for (int c = 0; c < 3; c++) {
        const float* im = x + ((size_t)b * 3 + c) * 448 * 448;
        float vll = (ylv && xlv) ? im[ylo * 448 + xlo] : 0.f;
        float vlh = (ylv && xhv) ? im[ylo * 448 + xho] : 0.f;
        float vhl = (yhv && xlv) ? im[yho * 448 + xlo] : 0.f;
        float vhh = (yhv && xhv) ? im[yho * 448 + xho] : 0.f;
        float top = (1.f - wx) * vll + wx * vlh;
        float bot = (1.f - wx) * vhl + wx * vhh;
        float v = (1.f - wy) * top + wy * bot;
        g_part[(((size_t)p * 3 + c) * 448 + i) * 448 + j] = v;
    }
}

// ---------------- launch ----------------
extern "C" void kernel_launch(void* const* d_in, const int* in_sizes, int n_in,
                              void* d_out, int out_size)
{
    const float* x     = (const float*)d_in[0];
    const float* stemw = (const float*)d_in[1];
    const float* stemb = (const float*)d_in[2];
    const float* fcw   = (const float*)d_in[3];
    const float* fcb   = (const float*)d_in[4];
    const float* d1w   = (const float*)d_in[5];
    const float* d1b   = (const float*)d_in[6];
    const float* d2w   = (const float*)d_in[7];
    const float* d2b   = (const float*)d_in[8];
    const float* d3w   = (const float*)d_in[9];
    const float* d3b   = (const float*)d_in[10];
    const float* t1w   = (const float*)d_in[11];
    const float* t1b   = (const float*)d_in[12];
    const float* t2w   = (const float*)d_in[13];
    const float* t2b   = (const float*)d_in[14];
    const float* t3w   = (const float*)d_in[15];
    const float* t3b   = (const float*)d_in[16];
    const float* cw    = (const float*)d_in[17];
    const float* cb    = (const float*)d_in[18];
    const float* pw    = (const float*)d_in[19];
    const float* pb    = (const float*)d_in[20];
    float* out = (float*)d_out;

    float *F8, *Fp, *Pimg, *PS, *D1, *D2, *D3, *G8, *GP, *RPN;
    cudaGetSymbolAddress((void**)&F8,  g_F8);
    cudaGetSymbolAddress((void**)&Fp,  g_Fp);
    cudaGetSymbolAddress((void**)&Pimg, g_part);
    cudaGetSymbolAddress((void**)&PS,  g_ps);
    cudaGetSymbolAddress((void**)&D1,  g_d1);
    cudaGetSymbolAddress((void**)&D2,  g_d2);
    cudaGetSymbolAddress((void**)&D3,  g_d3);
    cudaGetSymbolAddress((void**)&G8,  g_g8);
    cudaGetSymbolAddress((void**)&GP,  g_gp);
    cudaGetSymbolAddress((void**)&RPN, g_rpn);

    // anchors
    boxes_k<<<7, 256>>>();

    // stem on main images -> F8 (bias+relu fused)
    conv_gemm<3,7,7,32,3,448,448,14,14,1,1>
        <<<dim3(32, 4, NB), 256>>>(x, stemw, stemb, F8, 2048, NB);

    // global feature + raw logits
    mean_k<<<dim3(NB, 256), 256>>>(F8, G8, 196);
    fc_k<<<dim3(NB, 50), 128>>>(G8, fcw, fcb, out, 2048);

    // RPN tower (split-K=9 for occupancy)
    conv_gemm<2048,3,3,1,1,14,14,14,14,0,9>
        <<<dim3(2, 4, NB * 9), 256>>>(F8, d1w, nullptr, PS, 128, NB);
    reduce_br<<<(NB * 128 * 196 + 255) / 256, 256>>>(D1, PS, d1b, NB, 128, 196, 9);

    conv_gemm<128,3,3,2,1,14,14,7,7,0,9>
        <<<dim3(2, 1, NB * 9), 256>>>(D1, d2w, nullptr, PS, 128, NB);
    reduce_br<<<(NB * 128 * 49 + 255) / 256, 256>>>(D2, PS, d2b, NB, 128, 49, 9);

    conv_gemm<128,3,3,2,1,7,7,4,4,0,9>
        <<<dim3(2, 1, NB * 9), 256>>>(D2, d3w, nullptr, PS, 128, NB);
    reduce_br<<<(NB * 128 * 16 + 255) / 256, 256>>>(D3, PS, d3b, NB, 128, 16, 9);

    rpn_k<<<NB, 256>>>(D1, D2, D3, t1w, t1b, t2w, t2b, t3w, t3b, RPN);

    // top-4 NMS -> indices/probs (also written to output)
    nms_k<<<NB, 256>>>(RPN, out + 9600, out + 9632);

    // crop-resize parts
    crop_k<<<dim3(NPART, 448), 448>>>(x);

    // stem on part images -> Fp -> part features
    conv_gemm<3,7,7,32,3,448,448,14,14,1,1>
        <<<dim3(32, 4, NPART), 256>>>(Pimg, stemw, stemb, Fp, 2048, NPART);
    mean_k<<<dim3(NPART, 256), 256>>>(Fp, GP, 196);

    // heads
    fc_k<<<dim3(NPART, 50), 128>>>(GP, pw, pb, out + 3200, 2048);
    fc_concat_k<<<dim3(NB, 50), 128>>>(GP, G8, cw, cb, out + 1600);

    (void)in_sizes; (void)n_in; (void)out_size;
}

// round 2
// speedup vs baseline: 1.3186x; 1.3186x over previous
#include <cuda_runtime.h>
#include <math.h>
#include <stdint.h>

// ---------------- problem constants ----------------
#define NB    8
#define NPART 32
#define NANCH 1614
#define CAT   200
#define KPAD  152          // stem K=147 padded to multiple of 8
#define BSTRIDE 6272       // im2col column stride (part width 32*196); main uses [0,1600)

// output layout (float32, 9664 elems):
// [0,1600) raw_logits | [1600,3200) concat_logits | [3200,9600) part_logits
// [9600,9632) top_n_idx (float) | [9632,9664) top_n_prob

// ---------------- scratch ----------------
__device__ float g_F8 [NB    * 2048 * 196];
__device__ float g_Fp [NPART * 2048 * 196];
__device__ float g_part[NPART * 3 * 448 * 448];
__device__ float g_bcol[KPAD * BSTRIDE];
__device__ float g_wts [KPAD * 2048];
__device__ float g_wt1 [18432 * 128];
__device__ float g_wt2 [1152 * 128];
__device__ float g_wt3 [1152 * 128];
__device__ float g_ps  [12 * 128 * 1600];
__device__ float g_d1  [NB * 128 * 196];
__device__ float g_d2  [NB * 128 * 49];
__device__ float g_d3  [NB * 128 * 16];
__device__ float g_g8  [NB * 2048];
__device__ float g_gp  [NPART * 2048];
__device__ float g_cin [NB * 10240];
__device__ float g_rpn [NB * NANCH];
__device__ int   g_boxes[NANCH * 4];
__device__ float g_area [NANCH];
__device__ int   g_topidx[NB * 4];

// ---------------- anchors ----------------
__global__ void boxes_k()
{
    int a = blockIdx.x * blockDim.x + threadIdx.x;
    if (a >= NANCH) return;
    double CB1 = pow(2.0, 1.0 / 3.0);
    double CB2 = pow(2.0, 2.0 / 3.0);
    int stride, size, ow, scale_i, ar_i, cell;
    double s;
    if (a < 1176) {
        stride = 32; size = 48; ow = 14;
        int w = a; scale_i = w / (3 * 196); int r = w % (3 * 196);
        ar_i = r / 196; cell = r % 196;
        s = (scale_i == 0) ? CB1 : CB2;
    } else if (a < 1470) {
        stride = 64; size = 96; ow = 7;
        int w = a - 1176; scale_i = w / (3 * 49); int r = w % (3 * 49);
        ar_i = r / 49; cell = r % 49;
        s = (scale_i == 0) ? CB1 : CB2;
    } else {
        stride = 128; size = 192; ow = 4;
        int w = a - 1470; scale_i = w / (3 * 16); int r = w % (3 * 16);
        ar_i = r / 16; cell = r % 16;
        s = (scale_i == 0) ? 1.0 : ((scale_i == 1) ? CB1 : CB2);
    }
    double ar = (ar_i == 0) ? 0.667 : ((ar_i == 1) ? 1.0 : 1.5);
    int cyi = cell / ow, cxi = cell % ow;
    double cy = (double)cyi * stride + stride * 0.5;
    double cx = (double)cxi * stride + stride * 0.5;
    double sq = sqrt(ar);
    double hh = size * s / sq;
    double ww = size * s * sq;
    int y0 = (int)(cy - hh * 0.5 + 224.0);
    int x0 = (int)(cx - ww * 0.5 + 224.0);
    int y1 = (int)(cy + hh * 0.5 + 224.0);
    int x1 = (int)(cx + ww * 0.5 + 224.0);
    g_boxes[a * 4 + 0] = y0; g_boxes[a * 4 + 1] = x0;
    g_boxes[a * 4 + 2] = y1; g_boxes[a * 4 + 3] = x1;
    g_area[a] = (float)(y1 - y0) * (float)(x1 - x0);
}

// ---------------- weight transposes ----------------
__global__ void tr_stemw(const float* __restrict__ W, float* __restrict__ Wt)
{
    int idx = blockIdx.x * blockDim.x + threadIdx.x;
    if (idx >= KPAD * 2048) return;
    int k = idx >> 11, m = idx & 2047;
    Wt[idx] = (k < 147) ? W[(size_t)m * 147 + k] : 0.f;
}

template<int CIN>
__global__ void tr_dw(const float* __restrict__ W, float* __restrict__ Wt)
{
    int idx = blockIdx.x * blockDim.x + threadIdx.x;
    if (idx >= 9 * CIN * 128) return;
    int kt = idx >> 7, m = idx & 127;
    int tap = kt / CIN, ci = kt - tap * CIN;
    Wt[idx] = W[((size_t)m * CIN + ci) * 9 + tap];
}

// ---------------- im2col for the 7x7/s32 stem ----------------
__global__ void im2col_stem(const float* __restrict__ X, float* __restrict__ B,
                            int nimg, int ncols)
{
    int idx = blockIdx.x * blockDim.x + threadIdx.x;
    if (idx >= KPAD * ncols) return;
    int k = idx / ncols;
    int n = idx - k * ncols;
    float v = 0.f;
    if (k < 147) {
        int img = n / 196;
        if (img < nimg) {
            int pos = n - img * 196;
            int ci = k / 49;
            int r = k - ci * 49;
            int ky = r / 7, kx = r - ky * 7;
            int oy = pos / 14, ox = pos - oy * 14;
            int iy = oy * 32 - 3 + ky, ix = ox * 32 - 3 + kx;
            if (iy >= 0 && iy < 448 && ix >= 0 && ix < 448)
                v = X[((size_t)img * 3 + ci) * (448 * 448) + iy * 448 + ix];
        }
    }
    B[(size_t)k * BSTRIDE + n] = v;
}

// ---------------- stem GEMM: F = relu(W(2048xK) * B(KxN) + bias) ----------------
// 64x64 tiles, K=152 (19 chunks of 8), 256 threads, 4x4 register tiles, all float4.
__global__ __launch_bounds__(256)
void gemm_stem(const float* __restrict__ At, const float* __restrict__ B,
               const float* __restrict__ bias, float* __restrict__ OUT, int Nreal)
{
    const int m0 = blockIdx.x * 64;
    const int n0 = blockIdx.y * 64;
    __shared__ float4 As4[8][16];
    __shared__ float4 Bs4[8][16];
    float acc[4][4] = {};
    const int tid = threadIdx.x;
    const int tr = tid >> 4, tc = tid & 15;
    const int lr = (tid & 127) >> 4, lq = tid & 15;

    for (int k0 = 0; k0 < KPAD; k0 += 8) {
        if (tid < 128)
            As4[lr][lq] = *reinterpret_cast<const float4*>(&At[(size_t)(k0 + lr) * 2048 + m0 + lq * 4]);
        else
            Bs4[lr][lq] = *reinterpret_cast<const float4*>(&B[(size_t)(k0 + lr) * BSTRIDE + n0 + lq * 4]);
        __syncthreads();
#pragma unroll
        for (int kk = 0; kk < 8; kk++) {
            float4 a = As4[kk][tr];
            float4 b = Bs4[kk][tc];
            acc[0][0] += a.x * b.x; acc[0][1] += a.x * b.y; acc[0][2] += a.x * b.z; acc[0][3] += a.x * b.w;
            acc[1][0] += a.y * b.x; acc[1][1] += a.y * b.y; acc[1][2] += a.y * b.z; acc[1][3] += a.y * b.w;
            acc[2][0] += a.z * b.x; acc[2][1] += a.z * b.y; acc[2][2] += a.z * b.z; acc[2][3] += a.z * b.w;
            acc[3][0] += a.w * b.x; acc[3][1] += a.w * b.y; acc[3][2] += a.w * b.z; acc[3][3] += a.w * b.w;
        }
        __syncthreads();
    }
#pragma unroll
    for (int i = 0; i < 4; i++) {
        int gm = m0 + tr * 4 + i;
        float bv = bias[gm];
#pragma unroll
        for (int j = 0; j < 4; j++) {
            int n = n0 + tc * 4 + j;
            if (n < Nreal) {
                int img = n / 196;
                int pos = n - img * 196;
                OUT[((size_t)img * 2048 + gm) * 196 + pos] = fmaxf(acc[i][j] + bv, 0.f);
            }
        }
    }
}

// ---------------- implicit 3x3/pad1 conv (down tower), tap-major K ----------------
template<int CIN,int HIN,int WIN,int HOUT,int WOUT,int STRIDE,int SPLIT,int NPAD>
__global__ __launch_bounds__(256)
void dconv(const float* __restrict__ IN, const float* __restrict__ Wt,
           float* __restrict__ PART, int NIMG)
{
    constexpr int NCOL = HOUT * WOUT;
    constexpr int KTOT = 9 * CIN;
    constexpr int KS   = KTOT / SPLIT;
    const int sp = blockIdx.z;
    const int kbeg = sp * KS, kend = kbeg + KS;
    const int m0 = blockIdx.x * 64, n0 = blockIdx.y * 64;
    __shared__ float4 As4[8][16];
    __shared__ __align__(16) float Bs[8][64];
    float acc[4][4] = {};
    const int tid = threadIdx.x;
    const int tr = tid >> 4, tc = tid & 15;
    const int lr = (tid & 127) >> 4, lq = tid & 15;

    for (int k0 = kbeg; k0 < kend; k0 += 8) {
        if (tid < 128) {
            As4[lr][lq] = *reinterpret_cast<const float4*>(&Wt[(size_t)(k0 + lr) * 128 + m0 + lq * 4]);
        } else {
            int k = k0 + lr;
            int tap = k / CIN;
            int ci = k - tap * CIN;
            int ky = tap / 3 - 1, kx = tap - (tap / 3) * 3 - 1;
            const float* base = IN + (size_t)ci * (HIN * WIN);
#pragma unroll
            for (int e = 0; e < 4; e++) {
                int n = n0 + lq * 4 + e;
                int img = n / NCOL;
                int pos = n - img * NCOL;
                int oy = pos / WOUT, ox = pos - oy * WOUT;
                int iy = oy * STRIDE + ky, ix = ox * STRIDE + kx;
                float v = 0.f;
                if (img < NIMG && iy >= 0 && iy < HIN && ix >= 0 && ix < WIN)
                    v = __ldg(&base[(size_t)img * CIN * (HIN * WIN) + iy * WIN + ix]);
                Bs[lr][lq * 4 + e] = v;
            }
        }
        __syncthreads();
#pragma unroll
        for (int kk = 0; kk < 8; kk++) {
            float4 a = As4[kk][tr];
            float4 b = *reinterpret_cast<const float4*>(&Bs[kk][tc * 4]);
            acc[0][0] += a.x * b.x; acc[0][1] += a.x * b.y; acc[0][2] += a.x * b.z; acc[0][3] += a.x * b.w;
            acc[1][0] += a.y * b.x; acc[1][1] += a.y * b.y; acc[1][2] += a.y * b.z; acc[1][3] += a.y * b.w;
            acc[2][0] += a.z * b.x; acc[2][1] += a.z * b.y; acc[2][2] += a.z * b.z; acc[2][3] += a.z * b.w;
            acc[3][0] += a.w * b.x; acc[3][1] += a.w * b.y; acc[3][2] += a.w * b.z; acc[3][3] += a.w * b.w;
        }
        __syncthreads();
    }
#pragma unroll
    for (int i = 0; i < 4; i++) {
        int gm = m0 + tr * 4 + i;
#pragma unroll
        for (int j = 0; j < 4; j++) {
            int n = n0 + tc * 4 + j;
            PART[(size_t)(sp * 128 + gm) * NPAD + n] = acc[i][j];
        }
    }
}

// sum split-K partials + bias + relu -> [img][128][ncol]
__global__ void reduce_br(float* __restrict__ out, const float* __restrict__ part,
                          const float* __restrict__ bias, int nimg, int ncol,
                          int split, int npad)
{
    int idx = blockIdx.x * blockDim.x + threadIdx.x;
    int tot = nimg * 128 * ncol;
    if (idx >= tot) return;
    int img = idx / (128 * ncol);
    int r = idx - img * 128 * ncol;
    int m = r / ncol;
    int pos = r - m * ncol;
    int n = img * ncol + pos;
    float s = 0.f;
    for (int sp = 0; sp < split; sp++)
        s += part[(size_t)(sp * 128 + m) * npad + n];
    out[idx] = fmaxf(s + bias[m], 0.f);
}

// spatial mean
__global__ void mean_k(const float* __restrict__ F, float* __restrict__ G, int ncol)
{
    int img  = blockIdx.x;
    int oc   = blockIdx.y * 8 + (threadIdx.x >> 5);
    int lane = threadIdx.x & 31;
    const float* row = F + ((size_t)img * 2048 + oc) * ncol;
    float s = 0.f;
    for (int j = lane; j < ncol; j += 32) s += row[j];
#pragma unroll
    for (int o = 16; o; o >>= 1) s += __shfl_xor_sync(0xffffffffu, s, o);
    if (lane == 0) G[(size_t)img * 2048 + oc] = s / (float)ncol;
}

// FC: one class per block, 8 rows per block; W read once per (class,rowchunk)
__global__ void fc8(const float* __restrict__ G, const float* __restrict__ W,
                    const float* __restrict__ bias, float* __restrict__ out, int K)
{
    int cls = blockIdx.x;
    int rb  = blockIdx.y;
    const float* g = G + (size_t)rb * 8 * K;
    const float* w = W + (size_t)cls * K;
    float acc[8] = {};
    for (int k = threadIdx.x; k < K; k += 256) {
        float wv = w[k];
#pragma unroll
        for (int r = 0; r < 8; r++) acc[r] += wv * g[(size_t)r * K + k];
    }
    __shared__ float sm[8][8];
    int lane = threadIdx.x & 31, wid = threadIdx.x >> 5;
#pragma unroll
    for (int r = 0; r < 8; r++) {
        float s = acc[r];
#pragma unroll
        for (int o = 16; o; o >>= 1) s += __shfl_xor_sync(0xffffffffu, s, o);
        if (lane == 0) sm[wid][r] = s;
    }
    __syncthreads();
    if (threadIdx.x < 8) {
        int r = threadIdx.x;
        float s = 0.f;
#pragma unroll
        for (int w2 = 0; w2 < 8; w2++) s += sm[w2][r];
        out[(rb * 8 + r) * CAT + cls] = s + bias[cls];
    }
}

// build concat input rows: [part_feat(4x2048), global_feat(2048)] per image
__global__ void cin_k(const float* __restrict__ GP, const float* __restrict__ G8,
                      float* __restrict__ cin)
{
    int idx = blockIdx.x * blockDim.x + threadIdx.x;
    if (idx >= NB * 10240) return;
    int b = idx / 10240, k = idx - b * 10240;
    cin[idx] = (k < 8192) ? GP[(size_t)(b * 4 + (k >> 11)) * 2048 + (k & 2047)]
                          : G8[(size_t)b * 2048 + (k - 8192)];
}

// tidy 1x1 convs -> rpn scores
__global__ void rpn_k(const float* __restrict__ d1, const float* __restrict__ d2,
                      const float* __restrict__ d3,
                      const float* __restrict__ w1, const float* __restrict__ b1,
                      const float* __restrict__ w2, const float* __restrict__ b2,
                      const float* __restrict__ w3, const float* __restrict__ b3,
                      float* __restrict__ rpn)
{
    int img = blockIdx.x;
    for (int j = threadIdx.x; j < NANCH; j += blockDim.x) {
        float s;
        if (j < 1176) {
            int ch = j / 196, pos = j % 196;
            const float* in = d1 + (size_t)img * 128 * 196 + pos;
            const float* w  = w1 + ch * 128;
            s = b1[ch];
            for (int c = 0; c < 128; c++) s += in[c * 196] * w[c];
        } else if (j < 1470) {
            int jj = j - 1176;
            int ch = jj / 49, pos = jj % 49;
            const float* in = d2 + (size_t)img * 128 * 49 + pos;
            const float* w  = w2 + ch * 128;
            s = b2[ch];
            for (int c = 0; c < 128; c++) s += in[c * 49] * w[c];
        } else {
            int jj = j - 1470;
            int ch = jj / 16, pos = jj % 16;
            const float* in = d3 + (size_t)img * 128 * 16 + pos;
            const float* w  = w3 + ch * 128;
            s = b3[ch];
            for (int c = 0; c < 128; c++) s += in[c * 16] * w[c];
        }
        rpn[img * NANCH + j] = s;
    }
}

// NMS (first-index argmax tie-break)
__global__ void nms_k(const float* __restrict__ rpn,
                      float* __restrict__ out_idx_f, float* __restrict__ out_prob)
{
    int img = blockIdx.x;
    __shared__ float sc[NANCH];
    __shared__ unsigned char valid[NANCH];
    __shared__ float rv[256];
    __shared__ int   ri[256];
    __shared__ float pb[5];
    int tid = threadIdx.x;
    for (int j = tid; j < NANCH; j += 256) {
        sc[j] = rpn[img * NANCH + j];
        valid[j] = 1;
    }
    __syncthreads();
    for (int t = 0; t < 4; t++) {
        float bv = -INFINITY;
        int   bi = 0x7fffffff;
        for (int j = tid; j < NANCH; j += 256) {
            if (valid[j]) {
                float v = sc[j];
                if (v > bv || (v == bv && j < bi)) { bv = v; bi = j; }
            }
        }
        rv[tid] = bv; ri[tid] = bi;
        __syncthreads();
        for (int o = 128; o; o >>= 1) {
            if (tid < o) {
                float v2 = rv[tid + o]; int i2 = ri[tid + o];
                if (v2 > rv[tid] || (v2 == rv[tid] && i2 < ri[tid])) { rv[tid] = v2; ri[tid] = i2; }
            }
            __syncthreads();
        }
        if (tid == 0) {
            int p = ri[0];
            g_topidx[img * 4 + t] = p;
            out_idx_f[img * 4 + t] = (float)p;
            out_prob [img * 4 + t] = sc[p];
            pb[0] = (float)g_boxes[p * 4 + 0];
            pb[1] = (float)g_boxes[p * 4 + 1];
            pb[2] = (float)g_boxes[p * 4 + 2];
            pb[3] = (float)g_boxes[p * 4 + 3];
            pb[4] = g_area[p];
        }
        __syncthreads();
        float by0 = pb[0], bx0 = pb[1], by1 = pb[2], bx1 = pb[3], ba = pb[4];
        for (int j = tid; j < NANCH; j += 256) {
            if (!valid[j]) continue;
            float ty = fmaxf((float)g_boxes[j * 4 + 0], by0);
            float tx = fmaxf((float)g_boxes[j * 4 + 1], bx0);
            float cy = fminf((float)g_boxes[j * 4 + 2], by1);
            float cx = fminf((float)g_boxes[j * 4 + 3], bx1);
            float wh0 = cy - ty, wh1 = cx - tx;
            float inter = (wh0 < 0.f || wh1 < 0.f) ? 0.f : wh0 * wh1;
            float iou = inter / (g_area[j] + ba - inter);
            if (!(iou < 0.25f)) valid[j] = 0;
        }
        __syncthreads();
    }
}

// crop-resize
__global__ void crop_k(const float* __restrict__ x)
{
    int p = blockIdx.x;
    int i = blockIdx.y;
    int j = threadIdx.x;
    int b = p >> 2;
    int bi = g_topidx[p];
    int y0 = g_boxes[bi * 4 + 0], x0 = g_boxes[bi * 4 + 1];
    int y1 = g_boxes[bi * 4 + 2], x1 = g_boxes[bi * 4 + 3];
    if (y1 < y0 + 1) y1 = y0 + 1;
    if (x1 < x0 + 1) x1 = x0 + 1;
    float stepy = __fdiv_rn((float)(y1 - 1 - y0), 447.f);
    float stepx = __fdiv_rn((float)(x1 - 1 - x0), 447.f);
    float fy = __fadd_rn((float)y0, __fmul_rn((float)i, stepy));
    float fx = __fadd_rn((float)x0, __fmul_rn((float)j, stepx));
    int yl = (int)floorf(fy);
    int xl = (int)floorf(fx);
    int yh = yl + 1; if (yh > y1 - 1) yh = y1 - 1;
    int xh = xl + 1; if (xh > x1 - 1) xh = x1 - 1;
    float wy = fy - (float)yl;
    float wx = fx - (float)xl;
    int ylo = yl - 224, yho = yh - 224, xlo = xl - 224, xho = xh - 224;
    bool ylv = (ylo >= 0 && ylo < 448), yhv = (yho >= 0 && yho < 448);
    bool xlv = (xlo >= 0 && xlo < 448), xhv = (xho >= 0 && xho < 448);
#pragma unroll
    for (int c = 0; c < 3; c++) {
        const float* im = x + ((size_t)b * 3 + c) * 448 * 448;
        float vll = (ylv && xlv) ? im[ylo * 448 + xlo] : 0.f;
        float vlh = (ylv && xhv) ? im[ylo * 448 + xho] : 0.f;
        float vhl = (yhv && xlv) ? im[yho * 448 + xlo] : 0.f;
        float vhh = (yhv && xhv) ? im[yho * 448 + xho] : 0.f;
        float top = (1.f - wx) * vll + wx * vlh;
        float bot = (1.f - wx) * vhl + wx * vhh;
        g_part[(((size_t)p * 3 + c) * 448 + i) * 448 + j] = (1.f - wy) * top + wy * bot;
    }
}

// ---------------- launch ----------------
extern "C" void kernel_launch(void* const* d_in, const int* in_sizes, int n_in,
                              void* d_out, int out_size)
{
    const float* x     = (const float*)d_in[0];
    const float* stemw = (const float*)d_in[1];
    const float* stemb = (const float*)d_in[2];
    const float* fcw   = (const float*)d_in[3];
    const float* fcb   = (const float*)d_in[4];
    const float* d1w   = (const float*)d_in[5];
    const float* d1b   = (const float*)d_in[6];
    const float* d2w   = (const float*)d_in[7];
    const float* d2b   = (const float*)d_in[8];
    const float* d3w   = (const float*)d_in[9];
    const float* d3b   = (const float*)d_in[10];
    const float* t1w   = (const float*)d_in[11];
    const float* t1b   = (const float*)d_in[12];
    const float* t2w   = (const float*)d_in[13];
    const float* t2b   = (const float*)d_in[14];
    const float* t3w   = (const float*)d_in[15];
    const float* t3b   = (const float*)d_in[16];
    const float* cw    = (const float*)d_in[17];
    const float* cb    = (const float*)d_in[18];
    const float* pw    = (const float*)d_in[19];
    const float* pb    = (const float*)d_in[20];
    float* out = (float*)d_out;

    float *F8, *Fp, *Pimg, *BCOL, *WTS, *WT1, *WT2, *WT3, *PS;
    float *D1, *D2, *D3, *G8, *GP, *CIN_, *RPN;
    cudaGetSymbolAddress((void**)&F8,  g_F8);
    cudaGetSymbolAddress((void**)&Fp,  g_Fp);
    cudaGetSymbolAddress((void**)&Pimg, g_part);
    cudaGetSymbolAddress((void**)&BCOL, g_bcol);
    cudaGetSymbolAddress((void**)&WTS, g_wts);
    cudaGetSymbolAddress((void**)&WT1, g_wt1);
    cudaGetSymbolAddress((void**)&WT2, g_wt2);
    cudaGetSymbolAddress((void**)&WT3, g_wt3);
    cudaGetSymbolAddress((void**)&PS,  g_ps);
    cudaGetSymbolAddress((void**)&D1,  g_d1);
    cudaGetSymbolAddress((void**)&D2,  g_d2);
    cudaGetSymbolAddress((void**)&D3,  g_d3);
    cudaGetSymbolAddress((void**)&G8,  g_g8);
    cudaGetSymbolAddress((void**)&GP,  g_gp);
    cudaGetSymbolAddress((void**)&CIN_, g_cin);
    cudaGetSymbolAddress((void**)&RPN, g_rpn);

    boxes_k<<<7, 256>>>();
    tr_stemw<<<(KPAD * 2048 + 255) / 256, 256>>>(stemw, WTS);
    tr_dw<2048><<<(18432 * 128 + 255) / 256, 256>>>(d1w, WT1);
    tr_dw<128><<<(1152 * 128 + 255) / 256, 256>>>(d2w, WT2);
    tr_dw<128><<<(1152 * 128 + 255) / 256, 256>>>(d3w, WT3);

    // main stem: im2col -> one GEMM (N = 8*196 = 1568, padded to 1600)
    im2col_stem<<<(KPAD * 1600 + 255) / 256, 256>>>(x, BCOL, NB, 1600);
    gemm_stem<<<dim3(32, 25), 256>>>(WTS, BCOL, stemb, F8, 1568);
    mean_k<<<dim3(NB, 256), 256>>>(F8, G8, 196);
    fc8<<<dim3(CAT, 1), 256>>>(G8, fcw, fcb, out, 2048);

    // down tower, images batched into N, split-K
    dconv<2048,14,14,14,14,1,12,1600><<<dim3(2, 25, 12), 256>>>(F8, WT1, PS, NB);
    reduce_br<<<(NB * 128 * 196 + 255) / 256, 256>>>(D1, PS, d1b, NB, 196, 12, 1600);
    dconv<128,14,14,7,7,2,8,448><<<dim3(2, 7, 8), 256>>>(D1, WT2, PS, NB);
    reduce_br<<<(NB * 128 * 49 + 255) / 256, 256>>>(D2, PS, d2b, NB, 49, 8, 448);
    dconv<128,7,7,4,4,2,8,128><<<dim3(2, 2, 8), 256>>>(D2, WT3, PS, NB);
    reduce_br<<<(NB * 128 * 16 + 255) / 256, 256>>>(D3, PS, d3b, NB, 16, 8, 128);

    rpn_k<<<NB, 256>>>(D1, D2, D3, t1w, t1b, t2w, t2b, t3w, t3b, RPN);
    nms_k<<<NB, 256>>>(RPN, out + 9600, out + 9632);
    crop_k<<<dim3(NPART, 448), 448>>>(x);

    // part stem: im2col -> one GEMM (N = 32*196 = 6272)
    im2col_stem<<<(KPAD * 6272 + 255) / 256, 256>>>(Pimg, BCOL, NPART, 6272);
    gemm_stem<<<dim3(32, 98), 256>>>(WTS, BCOL, stemb, Fp, 6272);
    mean_k<<<dim3(NPART, 256), 256>>>(Fp, GP, 196);

    // heads
    fc8<<<dim3(CAT, 4), 256>>>(GP, pw, pb, out + 3200, 2048);
    cin_k<<<(NB * 10240 + 255) / 256, 256>>>(GP, G8, CIN_);
    fc8<<<dim3(CAT, 1), 256>>>(CIN_, cw, cb, out + 1600, 10240);

    (void)in_sizes; (void)n_in; (void)out_size;
}

// round 4
// speedup vs baseline: 1.8614x; 1.4117x over previous
#include <cuda_runtime.h>
#include <cuda_bf16.h>
#include <math.h>
#include <stdint.h>

// ---------------- problem constants ----------------
#define NB    8
#define NPART 32
#define NANCH 1614
#define CAT   200

#define KS3     576      // stem K' = 3*192
#define KSEG    192      // stem per-segment K (147 padded)
#define NMAIN   1568
#define NPMAIN  1664     // 13*128
#define NPART_N 6272     // 49*128
#define K1SEG   18432    // down1 per-segment K (9*2048)
#define K1TOT   55296    // 3*18432
#define D1SPLIT 12
#define D1KS    4608     // K1TOT / 12

// ---------------- scratch ----------------
__device__ float g_F8 [NB    * 2048 * 196];
__device__ float g_Fp [NPART * 2048 * 196];
__device__ float g_part[NPART * 3 * 448 * 448];
__device__ __nv_bfloat16 g_Ws  [2048 * KS3];        // stem weights, packed 3-seg [hi|hi|lo]
__device__ __nv_bfloat16 g_bc  [NPART_N * KS3];     // stem im2col, packed 3-seg [hi|lo|hi]
__device__ __nv_bfloat16 g_W1  [128 * K1TOT];       // down1 weights, packed 3-seg
__device__ __nv_bfloat16 g_Fthi[NMAIN * 2048];
__device__ __nv_bfloat16 g_Ftlo[NMAIN * 2048];
__device__ float g_wt2 [1152 * 128];
__device__ float g_wt3 [1152 * 128];
__device__ float g_ps  [D1SPLIT * 128 * NPMAIN];
__device__ float g_d1  [NB * 128 * 196];
__device__ float g_d2  [NB * 128 * 49];
__device__ float g_d3  [NB * 128 * 16];
__device__ float g_g8  [NB * 2048];
__device__ float g_gp  [NPART * 2048];
__device__ float g_cin [NB * 10240];
__device__ float g_rpn [NB * NANCH];
__device__ int   g_boxes[NANCH * 4];
__device__ float g_area [NANCH];
__device__ int   g_topidx[NB * 4];

// ---------------- PTX helpers (base sm_100-safe: ldmatrix + mma.sync only) ------
__device__ __forceinline__ uint32_t smem_u32(const void* p) {
    uint32_t a;
    asm("{ .reg .u64 t; cvta.to.shared.u64 t, %1; cvt.u32.u64 %0, t; }" : "=r"(a) : "l"(p));
    return a;
}
#define LDSM_X4(r, addr) \
    asm volatile("ldmatrix.sync.aligned.m8n8.x4.shared.b16 {%0,%1,%2,%3}, [%4];" \
        : "=r"((r)[0]), "=r"((r)[1]), "=r"((r)[2]), "=r"((r)[3]) : "r"(addr))
#define MMA16816(d, a, b0v, b1v) \
    asm volatile("mma.sync.aligned.m16n8k16.row.col.f32.bf16.bf16.f32 " \
        "{%0,%1,%2,%3}, {%4,%5,%6,%7}, {%8,%9}, {%0,%1,%2,%3};" \
        : "+f"((d)[0]), "+f"((d)[1]), "+f"((d)[2]), "+f"((d)[3]) \
        : "r"((a)[0]), "r"((a)[1]), "r"((a)[2]), "r"((a)[3]), "r"(b0v), "r"(b1v))

__device__ __forceinline__ void split_bf16(float v, __nv_bfloat16& hi, __nv_bfloat16& lo) {
    hi = __float2bfloat16(v);
    lo = __float2bfloat16(v - __bfloat162float(hi));
}

// ---------------- anchors ----------------
__global__ void boxes_k()
{
    int a = blockIdx.x * blockDim.x + threadIdx.x;
    if (a >= NANCH) return;
    double CB1 = pow(2.0, 1.0 / 3.0);
    double CB2 = pow(2.0, 2.0 / 3.0);
    int stride, size, ow, scale_i, ar_i, cell;
    double s;
    if (a < 1176) {
        stride = 32; size = 48; ow = 14;
        int w = a; scale_i = w / (3 * 196); int r = w % (3 * 196);
        ar_i = r / 196; cell = r % 196;
        s = (scale_i == 0) ? CB1 : CB2;
    } else if (a < 1470) {
        stride = 64; size = 96; ow = 7;
        int w = a - 1176; scale_i = w / (3 * 49); int r = w % (3 * 49);
        ar_i = r / 49; cell = r % 49;
        s = (scale_i == 0) ? CB1 : CB2;
    } else {
        stride = 128; size = 192; ow = 4;
        int w = a - 1470; scale_i = w / (3 * 16); int r = w % (3 * 16);
        ar_i = r / 16; cell = r % 16;
        s = (scale_i == 0) ? 1.0 : ((scale_i == 1) ? CB1 : CB2);
    }
    double ar = (ar_i == 0) ? 0.667 : ((ar_i == 1) ? 1.0 : 1.5);
    int cyi = cell / ow, cxi = cell % ow;
    double cy = (double)cyi * stride + stride * 0.5;
    double cx = (double)cxi * stride + stride * 0.5;
    double sq = sqrt(ar);
    double hh = size * s / sq;
    double ww = size * s * sq;
    int y0 = (int)(cy - hh * 0.5 + 224.0);
    int x0 = (int)(cx - ww * 0.5 + 224.0);
    int y1 = (int)(cy + hh * 0.5 + 224.0);
    int x1 = (int)(cx + ww * 0.5 + 224.0);
    g_boxes[a * 4 + 0] = y0; g_boxes[a * 4 + 1] = x0;
    g_boxes[a * 4 + 2] = y1; g_boxes[a * 4 + 3] = x1;
    g_area[a] = (float)(y1 - y0) * (float)(x1 - x0);
}

// ---------------- weight prep ----------------
__global__ void split_stemw(const float* __restrict__ W, __nv_bfloat16* __restrict__ O)
{
    int idx = blockIdx.x * blockDim.x + threadIdx.x;
    if (idx >= 2048 * KS3) return;
    int m = idx / KS3, kp = idx - m * KS3;
    int seg = kp / KSEG, kk = kp - seg * KSEG;
    float v = (kk < 147) ? W[(size_t)m * 147 + kk] : 0.f;
    __nv_bfloat16 hi, lo; split_bf16(v, hi, lo);
    O[idx] = (seg < 2) ? hi : lo;
}

__global__ void split_dw1(const float* __restrict__ W, __nv_bfloat16* __restrict__ O)
{
    int idx = blockIdx.x * blockDim.x + threadIdx.x;
    if (idx >= 128 * K1TOT) return;
    int m = idx / K1TOT, kp = idx - m * K1TOT;
    int seg = kp / K1SEG, kin = kp - seg * K1SEG;
    int tap = kin >> 11, ci = kin & 2047;
    float v = W[((size_t)m * 2048 + ci) * 9 + tap];
    __nv_bfloat16 hi, lo; split_bf16(v, hi, lo);
    O[idx] = (seg < 2) ? hi : lo;
}

template<int CIN>
__global__ void tr_dw(const float* __restrict__ W, float* __restrict__ Wt)
{
    int idx = blockIdx.x * blockDim.x + threadIdx.x;
    if (idx >= 9 * CIN * 128) return;
    int kt = idx >> 7, m = idx & 127;
    int tap = kt / CIN, ci = kt - tap * CIN;
    Wt[idx] = W[((size_t)m * CIN + ci) * 9 + tap];
}

// ---------------- stem im2col -> bc[n][k'] packed 3-seg [hi | lo | hi] ------------
__global__ void im2col_bf16(const float* __restrict__ X, __nv_bfloat16* __restrict__ B,
                            int nreal, int npad)
{
    int idx = blockIdx.x * blockDim.x + threadIdx.x;
    if (idx >= npad * KSEG) return;
    int n = idx / KSEG;
    int kk = idx - n * KSEG;
    float v = 0.f;
    if (kk < 147 && n < nreal) {
        int img = n / 196, pos = n - img * 196;
        int ci = kk / 49, r = kk - ci * 49;
        int ky = r / 7, kx = r - ky * 7;
        int oy = pos / 14, ox = pos - oy * 14;
        int iy = oy * 32 - 3 + ky, ix = ox * 32 - 3 + kx;
        if (iy >= 0 && iy < 448 && ix >= 0 && ix < 448)
            v = X[((size_t)img * 3 + ci) * (448 * 448) + iy * 448 + ix];
    }
    __nv_bfloat16 hi, lo; split_bf16(v, hi, lo);
    __nv_bfloat16* row = B + (size_t)n * KS3;
    row[kk] = hi; row[KSEG + kk] = lo; row[2 * KSEG + kk] = hi;
}

// ---------------- warp-MMA stem GEMM: OUT = relu(Ws(2048xK') * bc^T + bias) -------
// Block 128x128, 8 warps (warp tile 32x64), K chunks of 64, smem stride 72 bf16.
__global__ __launch_bounds__(256)
void mma_stem(const __nv_bfloat16* __restrict__ A, const __nv_bfloat16* __restrict__ B,
              const float* __restrict__ bias, float* __restrict__ OUT, int Nreal)
{
    __shared__ __align__(16) __nv_bfloat16 sA[128 * 72];
    __shared__ __align__(16) __nv_bfloat16 sB[128 * 72];
    const int tid = threadIdx.x, lane = tid & 31, wid = tid >> 5;
    const int wm = wid & 3, wn = wid >> 2;
    const int m0 = blockIdx.x * 128, n0 = blockIdx.y * 128;
    float acc[2][8][4] = {};

    const int arow = wm * 32 + (lane & 15);
    const int akoff = (lane >> 4) * 8;
    const int brow = wn * 64 + (lane & 7) + ((lane >> 4) & 1) * 8;
    const int bkoff = ((lane >> 3) & 1) * 8;

    for (int ch = 0; ch < 9; ch++) {
        const int k0 = ch * 64;
#pragma unroll
        for (int i = tid; i < 1024; i += 256) {
            int r = i >> 3, c = i & 7;
            *(uint4*)&sA[r * 72 + c * 8] =
                *(const uint4*)&A[(size_t)(m0 + r) * KS3 + k0 + c * 8];
            *(uint4*)&sB[r * 72 + c * 8] =
                *(const uint4*)&B[(size_t)(n0 + r) * KS3 + k0 + c * 8];
        }
        __syncthreads();
#pragma unroll
        for (int ks = 0; ks < 4; ks++) {
            uint32_t a[2][4], b[4][4];
            LDSM_X4(a[0], smem_u32(&sA[arow * 72 + ks * 16 + akoff]));
            LDSM_X4(a[1], smem_u32(&sA[(arow + 16) * 72 + ks * 16 + akoff]));
#pragma unroll
            for (int p = 0; p < 4; p++)
                LDSM_X4(b[p], smem_u32(&sB[(brow + p * 16) * 72 + ks * 16 + bkoff]));
#pragma unroll
            for (int mi = 0; mi < 2; mi++)
#pragma unroll
                for (int ni = 0; ni < 8; ni++)
                    MMA16816(acc[mi][ni], a[mi],
                             b[ni >> 1][(ni & 1) * 2], b[ni >> 1][(ni & 1) * 2 + 1]);
        }
        __syncthreads();
    }
    const int g = lane >> 2, tig = lane & 3;
#pragma unroll
    for (int mi = 0; mi < 2; mi++)
#pragma unroll
        for (int ni = 0; ni < 8; ni++)
#pragma unroll
            for (int e = 0; e < 4; e++) {
                int m = m0 + wm * 32 + mi * 16 + g + (e >> 1) * 8;
                int n = n0 + wn * 64 + ni * 8 + tig * 2 + (e & 1);
                if (n < Nreal) {
                    int img = n / 196, pos = n - img * 196;
                    OUT[((size_t)img * 2048 + m) * 196 + pos] =
                        fmaxf(acc[mi][ni][e] + bias[m], 0.f);
                }
            }
}

// ---------------- warp-MMA down1: PS[sp] = W1(128xK') * B^T (B gathered from Ft) --
__global__ __launch_bounds__(256)
void mma_down1(const __nv_bfloat16* __restrict__ A,
               const __nv_bfloat16* __restrict__ Fthi, const __nv_bfloat16* __restrict__ Ftlo,
               float* __restrict__ PS)
{
    __shared__ __align__(16) __nv_bfloat16 sA[128 * 72];
    __shared__ __align__(16) __nv_bfloat16 sB[128 * 72];
    const int tid = threadIdx.x, lane = tid & 31, wid = tid >> 5;
    const int wm = wid & 3, wn = wid >> 2;
    const int n0 = blockIdx.x * 128;
    const int sp = blockIdx.y;
    float acc[2][8][4] = {};

    // per-thread B gather geometry: rows tid>>3 + 32*j
    const int br0 = tid >> 3, bc8 = tid & 7;
    int bimg[4], boy[4], boxx[4];
    bool bnv[4];
#pragma unroll
    for (int j = 0; j < 4; j++) {
        int n = n0 + br0 + 32 * j;
        bnv[j] = (n < NMAIN);
        int img = n / 196, pos = n - img * 196;
        bimg[j] = img; boy[j] = pos / 14; boxx[j] = pos - (pos / 14) * 14;
    }

    const int arow = wm * 32 + (lane & 15);
    const int akoff = (lane >> 4) * 8;
    const int brow = wn * 64 + (lane & 7) + ((lane >> 4) & 1) * 8;
    const int bkoff = ((lane >> 3) & 1) * 8;
    const uint4 z4 = {0u, 0u, 0u, 0u};

    for (int ch = 0; ch < D1KS / 64; ch++) {
        const int k0p = sp * D1KS + ch * 64;
        const int seg = k0p / K1SEG;
        const int kin = k0p - seg * K1SEG;
        const int tap = kin >> 11, ci0 = kin & 2047;
        const int dy = tap / 3 - 1, dx = tap - (tap / 3) * 3 - 1;
        const __nv_bfloat16* plane = (seg == 1) ? Ftlo : Fthi;
#pragma unroll
        for (int i = tid; i < 1024; i += 256) {
            int r = i >> 3, c = i & 7;
            *(uint4*)&sA[r * 72 + c * 8] =
                *(const uint4*)&A[(size_t)r * K1TOT + k0p + c * 8];
        }
#pragma unroll
        for (int j = 0; j < 4; j++) {
            int iy = boy[j] + dy, ix = boxx[j] + dx;
            bool ok = bnv[j] && (unsigned)iy < 14u && (unsigned)ix < 14u;
            uint4 v = z4;
            if (ok)
                v = *(const uint4*)&plane[((size_t)(bimg[j] * 196 + iy * 14 + ix)) * 2048
                                          + ci0 + bc8 * 8];
            *(uint4*)&sB[(br0 + 32 * j) * 72 + bc8 * 8] = v;
        }
        __syncthreads();
#pragma unroll
        for (int ks = 0; ks < 4; ks++) {
            uint32_t a[2][4], b[4][4];
            LDSM_X4(a[0], smem_u32(&sA[arow * 72 + ks * 16 + akoff]));
            LDSM_X4(a[1], smem_u32(&sA[(arow + 16) * 72 + ks * 16 + akoff]));
#pragma unroll
            for (int p = 0; p < 4; p++)
                LDSM_X4(b[p], smem_u32(&sB[(brow + p * 16) * 72 + ks * 16 + bkoff]));
#pragma unroll
            for (int mi = 0; mi < 2; mi++)
#pragma unroll
                for (int ni = 0; ni < 8; ni++)
                    MMA16816(acc[mi][ni], a[mi],
                             b[ni >> 1][(ni & 1) * 2], b[ni >> 1][(ni & 1) * 2 + 1]);
        }
        __syncthreads();
    }
    const int g = lane >> 2, tig = lane & 3;
#pragma unroll
    for (int mi = 0; mi < 2; mi++)
#pragma unroll
        for (int ni = 0; ni < 8; ni++)
#pragma unroll
            for (int e = 0; e < 4; e++) {
                int m = wm * 32 + mi * 16 + g + (e >> 1) * 8;
                int n = n0 + wn * 64 + ni * 8 + tig * 2 + (e & 1);
                PS[(size_t)(sp * 128 + m) * NPMAIN + n] = acc[mi][ni][e];
            }
}

// ---------------- F8 -> Ft (n-major, c-contig) bf16 hi/lo split transpose --------
__global__ void ft_split(const float* __restrict__ F8,
                         __nv_bfloat16* __restrict__ Hi, __nv_bfloat16* __restrict__ Lo)
{
    __shared__ float sm[32][33];
    int c0 = blockIdx.x * 32, n0 = blockIdx.y * 32;
    int tx = threadIdx.x, ty = threadIdx.y;   // (32, 8)
#pragma unroll
    for (int i = 0; i < 4; i++) {
        int cl = ty + i * 8;
        int nn = n0 + tx;
        int img = nn / 196, pos = nn - img * 196;
        sm[cl][tx] = F8[((size_t)img * 2048 + c0 + cl) * 196 + pos];
    }
    __syncthreads();
#pragma unroll
    for (int i = 0; i < 4; i++) {
        int nl = ty + i * 8;
        int nn = n0 + nl, cc = c0 + tx;
        float v = sm[tx][nl];
        __nv_bfloat16 hi, lo; split_bf16(v, hi, lo);
        Hi[(size_t)nn * 2048 + cc] = hi;
        Lo[(size_t)nn * 2048 + cc] = lo;
    }
}

// ---------------- SIMT conv for down2/down3 (tiny) ----------------
template<int CIN,int HIN,int WIN,int HOUT,int WOUT,int STRIDE,int SPLIT,int NPAD>
__global__ __launch_bounds__(256)
void dconv(const float* __restrict__ IN, const float* __restrict__ Wt,
           float* __restrict__ PART, int NIMG)
{
    constexpr int NCOL = HOUT * WOUT;
    constexpr int KTOT = 9 * CIN;
    constexpr int KS   = KTOT / SPLIT;
    const int sp = blockIdx.z;
    const int kbeg = sp * KS, kend = kbeg + KS;
    const int m0 = blockIdx.x * 64, n0 = blockIdx.y * 64;
    __shared__ float4 As4[8][16];
    __shared__ __align__(16) float Bs[8][64];
    float acc[4][4] = {};
    const int tid = threadIdx.x;
    const int tr = tid >> 4, tc = tid & 15;
    const int lr = (tid & 127) >> 4, lq = tid & 15;

    for (int k0 = kbeg; k0 < kend; k0 += 8) {
        if (tid < 128) {
            As4[lr][lq] = *reinterpret_cast<const float4*>(&Wt[(size_t)(k0 + lr) * 128 + m0 + lq * 4]);
        } else {
            int k = k0 + lr;
            int tap = k / CIN;
            int ci = k - tap * CIN;
            int ky = tap / 3 - 1, kx = tap - (tap / 3) * 3 - 1;
            const float* base = IN + (size_t)ci * (HIN * WIN);
#pragma unroll
            for (int e = 0; e < 4; e++) {
                int n = n0 + lq * 4 + e;
                int img = n / NCOL;
                int pos = n - img * NCOL;
                int oy = pos / WOUT, ox = pos - oy * WOUT;
                int iy = oy * STRIDE + ky, ix = ox * STRIDE + kx;
                float v = 0.f;
                if (img < NIMG && iy >= 0 && iy < HIN && ix >= 0 && ix < WIN)
                    v = __ldg(&base[(size_t)img * CIN * (HIN * WIN) + iy * WIN + ix]);
                Bs[lr][lq * 4 + e] = v;
            }
        }
        __syncthreads();
#pragma unroll
        for (int kk = 0; kk < 8; kk++) {
            float4 a = As4[kk][tr];
            float4 b = *reinterpret_cast<const float4*>(&Bs[kk][tc * 4]);
            acc[0][0] += a.x * b.x; acc[0][1] += a.x * b.y; acc[0][2] += a.x * b.z; acc[0][3] += a.x * b.w;
            acc[1][0] += a.y * b.x; acc[1][1] += a.y * b.y; acc[1][2] += a.y * b.z; acc[1][3] += a.y * b.w;
            acc[2][0] += a.z * b.x; acc[2][1] += a.z * b.y; acc[2][2] += a.z * b.z; acc[2][3] += a.z * b.w;
            acc[3][0] += a.w * b.x; acc[3][1] += a.w * b.y; acc[3][2] += a.w * b.z; acc[3][3] += a.w * b.w;
        }
        __syncthreads();
    }
#pragma unroll
    for (int i = 0; i < 4; i++) {
        int gm = m0 + tr * 4 + i;
#pragma unroll
        for (int j = 0; j < 4; j++) {
            int n = n0 + tc * 4 + j;
            PART[(size_t)(sp * 128 + gm) * NPAD + n] = acc[i][j];
        }
    }
}

// sum split-K partials + bias + relu -> [img][128][ncol]
__global__ void reduce_br(float* __restrict__ out, const float* __restrict__ part,
                          const float* __restrict__ bias, int nimg, int ncol,
                          int split, int npad)
{
    int idx = blockIdx.x * blockDim.x + threadIdx.x;
    int tot = nimg * 128 * ncol;
    if (idx >= tot) return;
    int img = idx / (128 * ncol);
    int r = idx - img * 128 * ncol;
    int m = r / ncol;
    int pos = r - m * ncol;
    int n = img * ncol + pos;
    float s = 0.f;
    for (int sp = 0; sp < split; sp++)
        s += part[(size_t)(sp * 128 + m) * npad + n];
    out[idx] = fmaxf(s + bias[m], 0.f);
}

// spatial mean
__global__ void mean_k(const float* __restrict__ F, float* __restrict__ G, int ncol)
{
    int img  = blockIdx.x;
    int oc   = blockIdx.y * 8 + (threadIdx.x >> 5);
    int lane = threadIdx.x & 31;
    const float* row = F + ((size_t)img * 2048 + oc) * ncol;
    float s = 0.f;
    for (int j = lane; j < ncol; j += 32) s += row[j];
#pragma unroll
    for (int o = 16; o; o >>= 1) s += __shfl_xor_sync(0xffffffffu, s, o);
    if (lane == 0) G[(size_t)img * 2048 + oc] = s / (float)ncol;
}

// FC: one class per block, 8 rows per block
__global__ void fc8(const float* __restrict__ G, const float* __restrict__ W,
                    const float* __restrict__ bias, float* __restrict__ out, int K)
{
    int cls = blockIdx.x;
    int rb  = blockIdx.y;
    const float* g = G + (size_t)rb * 8 * K;
    const float* w = W + (size_t)cls * K;
    float acc[8] = {};
    for (int k = threadIdx.x; k < K; k += 256) {
        float wv = w[k];
#pragma unroll
        for (int r = 0; r < 8; r++) acc[r] += wv * g[(size_t)r * K + k];
    }
    __shared__ float sm[8][8];
    int lane = threadIdx.x & 31, wid = threadIdx.x >> 5;
#pragma unroll
    for (int r = 0; r < 8; r++) {
        float s = acc[r];
#pragma unroll
        for (int o = 16; o; o >>= 1) s += __shfl_xor_sync(0xffffffffu, s, o);
        if (lane == 0) sm[wid][r] = s;
    }
    __syncthreads();
    if (threadIdx.x < 8) {
        int r = threadIdx.x;
        float s = 0.f;
#pragma unroll
        for (int w2 = 0; w2 < 8; w2++) s += sm[w2][r];
        out[(rb * 8 + r) * CAT + cls] = s + bias[cls];
    }
}

__global__ void cin_k(const float* __restrict__ GP, const float* __restrict__ G8,
                      float* __restrict__ cin)
{
    int idx = blockIdx.x * blockDim.x + threadIdx.x;
    if (idx >= NB * 10240) return;
    int b = idx / 10240, k = idx - b * 10240;
    cin[idx] = (k < 8192) ? GP[(size_t)(b * 4 + (k >> 11)) * 2048 + (k & 2047)]
                          : G8[(size_t)b * 2048 + (k - 8192)];
}

// tidy 1x1 convs -> rpn scores
__global__ void rpn_k(const float* __restrict__ d1, const float* __restrict__ d2,
                      const float* __restrict__ d3,
                      const float* __restrict__ w1, const float* __restrict__ b1,
                      const float* __restrict__ w2, const float* __restrict__ b2,
                      const float* __restrict__ w3, const float* __restrict__ b3,
                      float* __restrict__ rpn)
{
    int img = blockIdx.x;
    int j = blockIdx.y * blockDim.x + threadIdx.x;
    if (j >= NANCH) return;
    float s;
    if (j < 1176) {
        int ch = j / 196, pos = j % 196;
        const float* in = d1 + (size_t)img * 128 * 196 + pos;
        const float* w  = w1 + ch * 128;
        s = b1[ch];
        for (int c = 0; c < 128; c++) s += in[c * 196] * w[c];
    } else if (j < 1470) {
        int jj = j - 1176;
        int ch = jj / 49, pos = jj % 49;
        const float* in = d2 + (size_t)img * 128 * 49 + pos;
        const float* w  = w2 + ch * 128;
        s = b2[ch];
        for (int c = 0; c < 128; c++) s += in[c * 49] * w[c];
    } else {
        int jj = j - 1470;
        int ch = jj / 16, pos = jj % 16;
        const float* in = d3 + (size_t)img * 128 * 16 + pos;
        const float* w  = w3 + ch * 128;
        s = b3[ch];
        for (int c = 0; c < 128; c++) s += in[c * 16] * w[c];
    }
    rpn[img * NANCH + j] = s;
}

// NMS (first-index argmax tie-break)
__global__ void nms_k(const float* __restrict__ rpn,
                      float* __restrict__ out_idx_f, float* __restrict__ out_prob)
{
    int img = blockIdx.x;
    __shared__ float sc[NANCH];
    __shared__ unsigned char valid[NANCH];
    __shared__ float rv[256];
    __shared__ int   ri[256];
    __shared__ float pb[5];
    int tid = threadIdx.x;
    for (int j = tid; j < NANCH; j += 256) {
        sc[j] = rpn[img * NANCH + j];
        valid[j] = 1;
    }
    __syncthreads();
    for (int t = 0; t < 4; t++) {
        float bv = -INFINITY;
        int   bi = 0x7fffffff;
        for (int j = tid; j < NANCH; j += 256) {
            if (valid[j]) {
                float v = sc[j];
                if (v > bv || (v == bv && j < bi)) { bv = v; bi = j; }
            }
        }
        rv[tid] = bv; ri[tid] = bi;
        __syncthreads();
        for (int o = 128; o; o >>= 1) {
            if (tid < o) {
                float v2 = rv[tid + o]; int i2 = ri[tid + o];
                if (v2 > rv[tid] || (v2 == rv[tid] && i2 < ri[tid])) { rv[tid] = v2; ri[tid] = i2; }
            }
            __syncthreads();
        }
        if (tid == 0) {
            int p = ri[0];
            g_topidx[img * 4 + t] = p;
            out_idx_f[img * 4 + t] = (float)p;
            out_prob [img * 4 + t] = sc[p];
            pb[0] = (float)g_boxes[p * 4 + 0];
            pb[1] = (float)g_boxes[p * 4 + 1];
            pb[2] = (float)g_boxes[p * 4 + 2];
            pb[3] = (float)g_boxes[p * 4 + 3];
            pb[4] = g_area[p];
        }
        __syncthreads();
        float by0 = pb[0], bx0 = pb[1], by1 = pb[2], bx1 = pb[3], ba = pb[4];
        for (int j = tid; j < NANCH; j += 256) {
            if (!valid[j]) continue;
            float ty = fmaxf((float)g_boxes[j * 4 + 0], by0);
            float tx = fmaxf((float)g_boxes[j * 4 + 1], bx0);
            float cy = fminf((float)g_boxes[j * 4 + 2], by1);
            float cx = fminf((float)g_boxes[j * 4 + 3], bx1);
            float wh0 = cy - ty, wh1 = cx - tx;
            float inter = (wh0 < 0.f || wh1 < 0.f) ? 0.f : wh0 * wh1;
            float iou = inter / (g_area[j] + ba - inter);
            if (!(iou < 0.25f)) valid[j] = 0;
        }
        __syncthreads();
    }
}

// crop-resize
__global__ void crop_k(const float* __restrict__ x)
{
    int p = blockIdx.x;
    int i = blockIdx.y;
    int j = threadIdx.x;
    int b = p >> 2;
    int bi = g_topidx[p];
    int y0 = g_boxes[bi * 4 + 0], x0 = g_boxes[bi * 4 + 1];
    int y1 = g_boxes[bi * 4 + 2], x1 = g_boxes[bi * 4 + 3];
    if (y1 < y0 + 1) y1 = y0 + 1;
    if (x1 < x0 + 1) x1 = x0 + 1;
    float stepy = __fdiv_rn((float)(y1 - 1 - y0), 447.f);
    float stepx = __fdiv_rn((float)(x1 - 1 - x0), 447.f);
    float fy = __fadd_rn((float)y0, __fmul_rn((float)i, stepy));
    float fx = __fadd_rn((float)x0, __fmul_rn((float)j, stepx));
    int yl = (int)floorf(fy);
    int xl = (int)floorf(fx);
    int yh = yl + 1; if (yh > y1 - 1) yh = y1 - 1;
    int xh = xl + 1; if (xh > x1 - 1) xh = x1 - 1;
    float wy = fy - (float)yl;
    float wx = fx - (float)xl;
    int ylo = yl - 224, yho = yh - 224, xlo = xl - 224, xho = xh - 224;
    bool ylv = (ylo >= 0 && ylo < 448), yhv = (yho >= 0 && yho < 448);
    bool xlv = (xlo >= 0 && xlo < 448), xhv = (xho >= 0 && xho < 448);
#pragma unroll
    for (int c = 0; c < 3; c++) {
        const float* im = x + ((size_t)b * 3 + c) * 448 * 448;
        float vll = (ylv && xlv) ? im[ylo * 448 + xlo] : 0.f;
        float vlh = (ylv && xhv) ? im[ylo * 448 + xho] : 0.f;
        float vhl = (yhv && xlv) ? im[yho * 448 + xlo] : 0.f;
        float vhh = (yhv && xhv) ? im[yho * 448 + xho] : 0.f;
        float top = (1.f - wx) * vll + wx * vlh;
        float bot = (1.f - wx) * vhl + wx * vhh;
        g_part[(((size_t)p * 3 + c) * 448 + i) * 448 + j] = (1.f - wy) * top + wy * bot;
    }
}

// ---------------- launch ----------------
extern "C" void kernel_launch(void* const* d_in, const int* in_sizes, int n_in,
                              void* d_out, int out_size)
{
    const float* x     = (const float*)d_in[0];
    const float* stemw = (const float*)d_in[1];
    const float* stemb = (const float*)d_in[2];
    const float* fcw   = (const float*)d_in[3];
    const float* fcb   = (const float*)d_in[4];
    const float* d1w   = (const float*)d_in[5];
    const float* d1b   = (const float*)d_in[6];
    const float* d2w   = (const float*)d_in[7];
    const float* d2b   = (const float*)d_in[8];
    const float* d3w   = (const float*)d_in[9];
    const float* d3b   = (const float*)d_in[10];
    const float* t1w   = (const float*)d_in[11];
    const float* t1b   = (const float*)d_in[12];
    const float* t2w   = (const float*)d_in[13];
    const float* t2b   = (const float*)d_in[14];
    const float* t3w   = (const float*)d_in[15];
    const float* t3b   = (const float*)d_in[16];
    const float* cw    = (const float*)d_in[17];
    const float* cb    = (const float*)d_in[18];
    const float* pw    = (const float*)d_in[19];
    const float* pb    = (const float*)d_in[20];
    float* out = (float*)d_out;

    float *F8, *Fp, *Pimg, *WT2, *WT3, *PS, *D1, *D2, *D3, *G8, *GP, *CIN_, *RPN;
    __nv_bfloat16 *WS, *BC, *W1, *FTH, *FTL;
    cudaGetSymbolAddress((void**)&F8,  g_F8);
    cudaGetSymbolAddress((void**)&Fp,  g_Fp);
    cudaGetSymbolAddress((void**)&Pimg, g_part);
    cudaGetSymbolAddress((void**)&WS,  g_Ws);
    cudaGetSymbolAddress((void**)&BC,  g_bc);
    cudaGetSymbolAddress((void**)&W1,  g_W1);
    cudaGetSymbolAddress((void**)&FTH, g_Fthi);
    cudaGetSymbolAddress((void**)&FTL, g_Ftlo);
    cudaGetSymbolAddress((void**)&WT2, g_wt2);
    cudaGetSymbolAddress((void**)&WT3, g_wt3);
    cudaGetSymbolAddress((void**)&PS,  g_ps);
    cudaGetSymbolAddress((void**)&D1,  g_d1);
    cudaGetSymbolAddress((void**)&D2,  g_d2);
    cudaGetSymbolAddress((void**)&D3,  g_d3);
    cudaGetSymbolAddress((void**)&G8,  g_g8);
    cudaGetSymbolAddress((void**)&GP,  g_gp);
    cudaGetSymbolAddress((void**)&CIN_, g_cin);
    cudaGetSymbolAddress((void**)&RPN, g_rpn);

    // 1..4: prep (ncu -s 5 -c 1 catches launch #5 = mma_stem main)
    boxes_k<<<7, 256>>>();
    split_stemw<<<(2048 * KS3 + 255) / 256, 256>>>(stemw, WS);
    split_dw1<<<(128 * K1TOT + 255) / 256, 256>>>(d1w, W1);
    im2col_bf16<<<(NPMAIN * KSEG + 255) / 256, 256>>>(x, BC, NMAIN, NPMAIN);

    // 5: main stem MMA (grid 16 x 13)
    mma_stem<<<dim3(16, 13), 256>>>(WS, BC, stemb, F8, NMAIN);

    // down tower
    ft_split<<<dim3(64, 49), dim3(32, 8)>>>(F8, FTH, FTL);
    mma_down1<<<dim3(13, D1SPLIT), 256>>>(W1, FTH, FTL, PS);
    reduce_br<<<(NB * 128 * 196 + 255) / 256, 256>>>(D1, PS, d1b, NB, 196, D1SPLIT, NPMAIN);

    tr_dw<128><<<(1152 * 128 + 255) / 256, 256>>>(d2w, WT2);
    tr_dw<128><<<(1152 * 128 + 255) / 256, 256>>>(d3w, WT3);
    dconv<128,14,14,7,7,2,8,448><<<dim3(2, 7, 8), 256>>>(D1, WT2, PS, NB);
    reduce_br<<<(NB * 128 * 49 + 255) / 256, 256>>>(D2, PS, d2b, NB, 49, 8, 448);
    dconv<128,7,7,4,4,2,8,128><<<dim3(2, 2, 8), 256>>>(D2, WT3, PS, NB);
    reduce_br<<<(NB * 128 * 16 + 255) / 256, 256>>>(D3, PS, d3b, NB, 16, 8, 128);

    mean_k<<<dim3(NB, 256), 256>>>(F8, G8, 196);
    fc8<<<dim3(CAT, 1), 256>>>(G8, fcw, fcb, out, 2048);

    rpn_k<<<dim3(NB, 7), 256>>>(D1, D2, D3, t1w, t1b, t2w, t2b, t3w, t3b, RPN);
    nms_k<<<NB, 256>>>(RPN, out + 9600, out + 9632);
    crop_k<<<dim3(NPART, 448), 448>>>(x);

    // part stem (grid 16 x 49)
    im2col_bf16<<<(NPART_N * KSEG + 255) / 256, 256>>>(Pimg, BC, NPART_N, NPART_N);
    mma_stem<<<dim3(16, 49), 256>>>(WS, BC, stemb, Fp, NPART_N);
    mean_k<<<dim3(NPART, 256), 256>>>(Fp, GP, 196);

    // heads
    fc8<<<dim3(CAT, 4), 256>>>(GP, pw, pb, out + 3200, 2048);
    cin_k<<<(NB * 10240 + 255) / 256, 256>>>(GP, G8, CIN_);
    fc8<<<dim3(CAT, 1), 256>>>(CIN_, cw, cb, out + 1600, 10240);

    (void)in_sizes; (void)n_in; (void)out_size;
}

// round 5
// speedup vs baseline: 2.3226x; 1.2478x over previous
#include <cuda_runtime.h>
#include <cuda_bf16.h>
#include <math.h>
#include <stdint.h>

// ---------------- problem constants ----------------
#define NB    8
#define NPART 32
#define NANCH 1614
#define CAT   200

#define KS3     576      // stem K' = 3*192
#define KSEG    192      // stem per-segment K (147 padded)
#define NMAIN   1568
#define NPMAIN  1664     // 13*128
#define NPART_N 6272     // 49*128
#define K1SEG   18432    // down1 per-segment K (9*2048)
#define K1TOT   55296    // 3*18432
#define D1SPLIT 12
#define D1KS    4608     // K1TOT / 12

// ---------------- scratch ----------------
__device__ __nv_bfloat16 g_Ws  [2048 * KS3];        // stem weights [hi|hi|lo]
__device__ __nv_bfloat16 g_bc  [NPART_N * KS3];     // stem im2col [hi|lo|hi]
__device__ __nv_bfloat16 g_W1  [128 * K1TOT];       // down1 weights [hi|hi|lo]
__device__ __nv_bfloat16 g_Fthi[NMAIN * 2048];      // stem features (transposed, hi)
__device__ __nv_bfloat16 g_Ftlo[NMAIN * 2048];      // stem features (transposed, lo)
__device__ float g_wt2 [1152 * 128];
__device__ float g_wt3 [1152 * 128];
__device__ float g_ps  [D1SPLIT * 128 * NPMAIN];
__device__ float g_d1  [NB * 128 * 196];
__device__ float g_d2  [NB * 128 * 49];
__device__ float g_d3  [NB * 128 * 16];
__device__ float g_g8  [NB * 2048];
__device__ float g_gp  [NPART * 2048];
__device__ float g_cin [NB * 10240];
__device__ float g_rpn [NB * NANCH];
__device__ int   g_boxes[NANCH * 4];
__device__ float g_area [NANCH];
__device__ int   g_topidx[NB * 4];

// ---------------- PTX helpers ----------------
__device__ __forceinline__ uint32_t smem_u32(const void* p) {
    uint32_t a;
    asm("{ .reg .u64 t; cvta.to.shared.u64 t, %1; cvt.u32.u64 %0, t; }" : "=r"(a) : "l"(p));
    return a;
}
#define LDSM_X4(r, addr) \
    asm volatile("ldmatrix.sync.aligned.m8n8.x4.shared.b16 {%0,%1,%2,%3}, [%4];" \
        : "=r"((r)[0]), "=r"((r)[1]), "=r"((r)[2]), "=r"((r)[3]) : "r"(addr))
#define MMA16816(d, a, b0v, b1v) \
    asm volatile("mma.sync.aligned.m16n8k16.row.col.f32.bf16.bf16.f32 " \
        "{%0,%1,%2,%3}, {%4,%5,%6,%7}, {%8,%9}, {%0,%1,%2,%3};" \
        : "+f"((d)[0]), "+f"((d)[1]), "+f"((d)[2]), "+f"((d)[3]) \
        : "r"((a)[0]), "r"((a)[1]), "r"((a)[2]), "r"((a)[3]), "r"(b0v), "r"(b1v))

__device__ __forceinline__ void split_bf16(float v, __nv_bfloat16& hi, __nv_bfloat16& lo) {
    hi = __float2bfloat16(v);
    lo = __float2bfloat16(v - __bfloat162float(hi));
}

// ---------------- zero pooled-feature accumulators ----------------
__global__ void zero_k(float* g8, float* gp)
{
    int i = blockIdx.x * blockDim.x + threadIdx.x;
    if (i < NB * 2048) g8[i] = 0.f;
    if (i < NPART * 2048) gp[i] = 0.f;
}

// ---------------- anchors ----------------
__global__ void boxes_k()
{
    int a = blockIdx.x * blockDim.x + threadIdx.x;
    if (a >= NANCH) return;
    double CB1 = pow(2.0, 1.0 / 3.0);
    double CB2 = pow(2.0, 2.0 / 3.0);
    int stride, size, ow, scale_i, ar_i, cell;
    double s;
    if (a < 1176) {
        stride = 32; size = 48; ow = 14;
        int w = a; scale_i = w / (3 * 196); int r = w % (3 * 196);
        ar_i = r / 196; cell = r % 196;
        s = (scale_i == 0) ? CB1 : CB2;
    } else if (a < 1470) {
        stride = 64; size = 96; ow = 7;
        int w = a - 1176; scale_i = w / (3 * 49); int r = w % (3 * 49);
        ar_i = r / 49; cell = r % 49;
        s = (scale_i == 0) ? CB1 : CB2;
    } else {
        stride = 128; size = 192; ow = 4;
        int w = a - 1470; scale_i = w / (3 * 16); int r = w % (3 * 16);
        ar_i = r / 16; cell = r % 16;
        s = (scale_i == 0) ? 1.0 : ((scale_i == 1) ? CB1 : CB2);
    }
    double ar = (ar_i == 0) ? 0.667 : ((ar_i == 1) ? 1.0 : 1.5);
    int cyi = cell / ow, cxi = cell % ow;
    double cy = (double)cyi * stride + stride * 0.5;
    double cx = (double)cxi * stride + stride * 0.5;
    double sq = sqrt(ar);
    double hh = size * s / sq;
    double ww = size * s * sq;
    int y0 = (int)(cy - hh * 0.5 + 224.0);
    int x0 = (int)(cx - ww * 0.5 + 224.0);
    int y1 = (int)(cy + hh * 0.5 + 224.0);
    int x1 = (int)(cx + ww * 0.5 + 224.0);
    g_boxes[a * 4 + 0] = y0; g_boxes[a * 4 + 1] = x0;
    g_boxes[a * 4 + 2] = y1; g_boxes[a * 4 + 3] = x1;
    g_area[a] = (float)(y1 - y0) * (float)(x1 - x0);
}

// ---------------- weight prep ----------------
__global__ void split_stemw(const float* __restrict__ W, __nv_bfloat16* __restrict__ O)
{
    int idx = blockIdx.x * blockDim.x + threadIdx.x;
    if (idx >= 2048 * KS3) return;
    int m = idx / KS3, kp = idx - m * KS3;
    int seg = kp / KSEG, kk = kp - seg * KSEG;
    float v = (kk < 147) ? W[(size_t)m * 147 + kk] : 0.f;
    __nv_bfloat16 hi, lo; split_bf16(v, hi, lo);
    O[idx] = (seg < 2) ? hi : lo;
}

__global__ void split_dw1(const float* __restrict__ W, __nv_bfloat16* __restrict__ O)
{
    int idx = blockIdx.x * blockDim.x + threadIdx.x;
    if (idx >= 128 * K1TOT) return;
    int m = idx / K1TOT, kp = idx - m * K1TOT;
    int seg = kp / K1SEG, kin = kp - seg * K1SEG;
    int tap = kin >> 11, ci = kin & 2047;
    float v = W[((size_t)m * 2048 + ci) * 9 + tap];
    __nv_bfloat16 hi, lo; split_bf16(v, hi, lo);
    O[idx] = (seg < 2) ? hi : lo;
}

template<int CIN>
__global__ void tr_dw(const float* __restrict__ W, float* __restrict__ Wt)
{
    int idx = blockIdx.x * blockDim.x + threadIdx.x;
    if (idx >= 9 * CIN * 128) return;
    int kt = idx >> 7, m = idx & 127;
    int tap = kt / CIN, ci = kt - tap * CIN;
    Wt[idx] = W[((size_t)m * CIN + ci) * 9 + tap];
}

// ---------------- main stem im2col -> bc[n][k'] [hi | lo | hi] ----------------
__global__ void im2col_bf16(const float* __restrict__ X, __nv_bfloat16* __restrict__ B,
                            int nreal, int npad)
{
    int idx = blockIdx.x * blockDim.x + threadIdx.x;
    if (idx >= npad * KSEG) return;
    int n = idx / KSEG;
    int kk = idx - n * KSEG;
    float v = 0.f;
    if (kk < 147 && n < nreal) {
        int img = n / 196, pos = n - img * 196;
        int ci = kk / 49, r = kk - ci * 49;
        int ky = r / 7, kx = r - ky * 7;
        int oy = pos / 14, ox = pos - oy * 14;
        int iy = oy * 32 - 3 + ky, ix = ox * 32 - 3 + kx;
        if (iy >= 0 && iy < 448 && ix >= 0 && ix < 448)
            v = X[((size_t)img * 3 + ci) * (448 * 448) + iy * 448 + ix];
    }
    __nv_bfloat16 hi, lo; split_bf16(v, hi, lo);
    __nv_bfloat16* row = B + (size_t)n * KS3;
    row[kk] = hi; row[KSEG + kk] = lo; row[2 * KSEG + kk] = hi;
}

// ---------------- fused crop-resize + im2col for part stem --------------------
// B col n = (part p, pos); tap kk -> sample part image at (iy, ix); part image
// pixel = bilinear crop of x (with pad-224 and zero outside) -- computed inline.
__global__ void part_bcol(const float* __restrict__ x, __nv_bfloat16* __restrict__ B)
{
    int idx = blockIdx.x * blockDim.x + threadIdx.x;
    if (idx >= NPART_N * KSEG) return;
    int n = idx / KSEG;
    int kk = idx - n * KSEG;
    float v = 0.f;
    if (kk < 147) {
        int p = n / 196, pos = n - p * 196;
        int ci = kk / 49, r = kk - ci * 49;
        int ky = r / 7, kx = r - ky * 7;
        int oy = pos / 14, ox = pos - oy * 14;
        int iy = oy * 32 - 3 + ky, ix = ox * 32 - 3 + kx;
        if (iy >= 0 && iy < 448 && ix >= 0 && ix < 448) {
            int b = p >> 2;
            int bi = g_topidx[p];
            int y0 = g_boxes[bi * 4 + 0], x0 = g_boxes[bi * 4 + 1];
            int y1 = g_boxes[bi * 4 + 2], x1 = g_boxes[bi * 4 + 3];
            if (y1 < y0 + 1) y1 = y0 + 1;
            if (x1 < x0 + 1) x1 = x0 + 1;
            float stepy = __fdiv_rn((float)(y1 - 1 - y0), 447.f);
            float stepx = __fdiv_rn((float)(x1 - 1 - x0), 447.f);
            float fy = __fadd_rn((float)y0, __fmul_rn((float)iy, stepy));
            float fx = __fadd_rn((float)x0, __fmul_rn((float)ix, stepx));
            int yl = (int)floorf(fy);
            int xl = (int)floorf(fx);
            int yh = yl + 1; if (yh > y1 - 1) yh = y1 - 1;
            int xh = xl + 1; if (xh > x1 - 1) xh = x1 - 1;
            float wy = fy - (float)yl;
            float wx = fx - (float)xl;
            int ylo = yl - 224, yho = yh - 224, xlo = xl - 224, xho = xh - 224;
            bool ylv = (ylo >= 0 && ylo < 448), yhv = (yho >= 0 && yho < 448);
            bool xlv = (xlo >= 0 && xlo < 448), xhv = (xho >= 0 && xho < 448);
            const float* im = x + ((size_t)b * 3 + ci) * 448 * 448;
            float vll = (ylv && xlv) ? im[ylo * 448 + xlo] : 0.f;
            float vlh = (ylv && xhv) ? im[ylo * 448 + xho] : 0.f;
            float vhl = (yhv && xlv) ? im[yho * 448 + xlo] : 0.f;
            float vhh = (yhv && xhv) ? im[yho * 448 + xho] : 0.f;
            float top = (1.f - wx) * vll + wx * vlh;
            float bot = (1.f - wx) * vhl + wx * vhh;
            v = (1.f - wy) * top + wy * bot;
        }
    }
    __nv_bfloat16 hi, lo; split_bf16(v, hi, lo);
    __nv_bfloat16* row = B + (size_t)n * KS3;
    row[kk] = hi; row[KSEG + kk] = lo; row[2 * KSEG + kk] = hi;
}

// ---------------- warp-MMA stem GEMM with fused pooling (+optional Ft store) ----
// Block 128x128, 8 warps, K chunks of 64, register-prefetch pipelined.
template<int WRITE_FT>
__global__ __launch_bounds__(256)
void mma_stem(const __nv_bfloat16* __restrict__ A, const __nv_bfloat16* __restrict__ B,
              const float* __restrict__ bias, float* __restrict__ G,
              __nv_bfloat16* __restrict__ FtHi, __nv_bfloat16* __restrict__ FtLo,
              int Nreal, int nimg)
{
    __shared__ __align__(16) __nv_bfloat16 sA[128 * 72];
    __shared__ __align__(16) __nv_bfloat16 sB[128 * 72];
    __shared__ float pbuf[256];
    const int tid = threadIdx.x, lane = tid & 31, wid = tid >> 5;
    const int wm = wid & 3, wn = wid >> 2;
    const int m0 = blockIdx.x * 128, n0 = blockIdx.y * 128;
    float acc[2][8][4] = {};

    const int rbase = tid >> 3, c8 = tid & 7;
    const int arow = wm * 32 + (lane & 15);
    const int akoff = (lane >> 4) * 8;
    const int brow = wn * 64 + (lane & 7) + ((lane >> 4) & 1) * 8;
    const int bkoff = ((lane >> 3) & 1) * 8;

    uint4 ra[4], rb[4];
#pragma unroll
    for (int j = 0; j < 4; j++) {
        ra[j] = *(const uint4*)&A[(size_t)(m0 + rbase + 32 * j) * KS3 + c8 * 8];
        rb[j] = *(const uint4*)&B[(size_t)(n0 + rbase + 32 * j) * KS3 + c8 * 8];
    }
    for (int ch = 0; ch < 9; ch++) {
#pragma unroll
        for (int j = 0; j < 4; j++) {
            int off = (rbase + 32 * j) * 72 + c8 * 8;
            *(uint4*)&sA[off] = ra[j];
            *(uint4*)&sB[off] = rb[j];
        }
        __syncthreads();
        if (ch < 8) {
            const int k0 = (ch + 1) * 64;
#pragma unroll
            for (int j = 0; j < 4; j++) {
                ra[j] = *(const uint4*)&A[(size_t)(m0 + rbase + 32 * j) * KS3 + k0 + c8 * 8];
                rb[j] = *(const uint4*)&B[(size_t)(n0 + rbase + 32 * j) * KS3 + k0 + c8 * 8];
            }
        }
#pragma unroll
        for (int ks = 0; ks < 4; ks++) {
            uint32_t a[2][4], b[4][4];
            LDSM_X4(a[0], smem_u32(&sA[arow * 72 + ks * 16 + akoff]));
            LDSM_X4(a[1], smem_u32(&sA[(arow + 16) * 72 + ks * 16 + akoff]));
#pragma unroll
            for (int p = 0; p < 4; p++)
                LDSM_X4(b[p], smem_u32(&sB[(brow + p * 16) * 72 + ks * 16 + bkoff]));
#pragma unroll
            for (int mi = 0; mi < 2; mi++)
#pragma unroll
                for (int ni = 0; ni < 8; ni++)
                    MMA16816(acc[mi][ni], a[mi],
                             b[ni >> 1][(ni & 1) * 2], b[ni >> 1][(ni & 1) * 2 + 1]);
        }
        __syncthreads();
    }

    // ---- epilogue ----
    const int g = lane >> 2, tig = lane & 3;
    float bv[2][2];
#pragma unroll
    for (int mi = 0; mi < 2; mi++)
#pragma unroll
        for (int h = 0; h < 2; h++)
            bv[mi][h] = bias[m0 + wm * 32 + mi * 16 + g + h * 8];

    // pooled mean accumulation (relu(acc+bias)/196 summed per image)
    pbuf[tid] = 0.f;
    __syncthreads();
    const int imgA = n0 / 196;
    const int bnd = (imgA + 1) * 196;
    float ps[2][2][2] = {};
#pragma unroll
    for (int mi = 0; mi < 2; mi++)
#pragma unroll
        for (int ni = 0; ni < 8; ni++)
#pragma unroll
            for (int e = 0; e < 4; e++) {
                int n = n0 + wn * 64 + ni * 8 + tig * 2 + (e & 1);
                if (n < Nreal) {
                    float v = fmaxf(acc[mi][ni][e] + bv[mi][e >> 1], 0.f);
                    ps[mi][e >> 1][n >= bnd ? 1 : 0] += v;
                }
            }
#pragma unroll
    for (int mi = 0; mi < 2; mi++)
#pragma unroll
        for (int h = 0; h < 2; h++)
#pragma unroll
            for (int s = 0; s < 2; s++)
                atomicAdd(&pbuf[s * 128 + wm * 32 + mi * 16 + g + h * 8],
                          ps[mi][h][s] * (1.f / 196.f));
    __syncthreads();
    {
        int s = tid >> 7, m = tid & 127;
        int img = imgA + s;
        if (img < nimg)
            atomicAdd(&G[(size_t)img * 2048 + m0 + m], pbuf[tid]);
    }

    if (WRITE_FT) {
        float* tbuf = (float*)sA;   // 32 x 132 floats = 16.9 KB (fits in sA)
        for (int p = 0; p < 4; p++) {
            __syncthreads();
#pragma unroll
            for (int mi = 0; mi < 2; mi++)
#pragma unroll
                for (int ni = 0; ni < 8; ni++)
#pragma unroll
                    for (int e = 0; e < 4; e++) {
                        int n = n0 + wn * 64 + ni * 8 + tig * 2 + (e & 1);
                        int dn = n - n0 - p * 32;
                        if (dn >= 0 && dn < 32 && n < Nreal)
                            tbuf[dn * 132 + wm * 32 + mi * 16 + g + (e >> 1) * 8] =
                                fmaxf(acc[mi][ni][e] + bv[mi][e >> 1], 0.f);
                    }
            __syncthreads();
            int nl = tid >> 3, mb = (tid & 7) * 16;
            int n = n0 + p * 32 + nl;
            if (n < Nreal) {
                __align__(16) __nv_bfloat16 hi[16], lo[16];
#pragma unroll
                for (int q = 0; q < 16; q++)
                    split_bf16(tbuf[nl * 132 + mb + q], hi[q], lo[q]);
                *(uint4*)&FtHi[(size_t)n * 2048 + m0 + mb]     = *(uint4*)hi;
                *(uint4*)&FtHi[(size_t)n * 2048 + m0 + mb + 8] = *(uint4*)(hi + 8);
                *(uint4*)&FtLo[(size_t)n * 2048 + m0 + mb]     = *(uint4*)lo;
                *(uint4*)&FtLo[(size_t)n * 2048 + m0 + mb + 8] = *(uint4*)(lo + 8);
            }
        }
    }
}

// ---------------- warp-MMA down1: PS[sp] = W1(128xK') * B^T (B from Ft) --------
__global__ __launch_bounds__(256)
void mma_down1(const __nv_bfloat16* __restrict__ A,
               const __nv_bfloat16* __restrict__ Fthi, const __nv_bfloat16* __restrict__ Ftlo,
               float* __restrict__ PS)
{
    __shared__ __align__(16) __nv_bfloat16 sA[128 * 72];
    __shared__ __align__(16) __nv_bfloat16 sB[128 * 72];
    const int tid = threadIdx.x, lane = tid & 31, wid = tid >> 5;
    const int wm = wid & 3, wn = wid >> 2;
    const int n0 = blockIdx.x * 128;
    const int sp = blockIdx.y;
    float acc[2][8][4] = {};

    const int rbase = tid >> 3, c8 = tid & 7;
    int bimg[4], boy[4], boxx[4];
    bool bnv[4];
#pragma unroll
    for (int j = 0; j < 4; j++) {
        int n = n0 + rbase + 32 * j;
        bnv[j] = (n < NMAIN);
        int img = n / 196, pos = n - img * 196;
        bimg[j] = img; boy[j] = pos / 14; boxx[j] = pos - (pos / 14) * 14;
    }

    const int arow = wm * 32 + (lane & 15);
    const int akoff = (lane >> 4) * 8;
    const int brow = wn * 64 + (lane & 7) + ((lane >> 4) & 1) * 8;
    const int bkoff = ((lane >> 3) & 1) * 8;
    const uint4 z4 = {0u, 0u, 0u, 0u};

    auto loadB = [&](int ch, uint4 rbv[4]) {
        const int k0p = sp * D1KS + ch * 64;
        const int seg = k0p / K1SEG;
        const int kin = k0p - seg * K1SEG;
        const int tap = kin >> 11, ci0 = kin & 2047;
        const int dy = tap / 3 - 1, dx = tap - (tap / 3) * 3 - 1;
        const __nv_bfloat16* plane = (seg == 1) ? Ftlo : Fthi;
#pragma unroll
        for (int j = 0; j < 4; j++) {
            int iy = boy[j] + dy, ix = boxx[j] + dx;
            bool ok = bnv[j] && (unsigned)iy < 14u && (unsigned)ix < 14u;
            rbv[j] = ok
                ? *(const uint4*)&plane[((size_t)(bimg[j] * 196 + iy * 14 + ix)) * 2048
                                        + ci0 + c8 * 8]
                : z4;
        }
    };

    uint4 ra[4], rb[4];
    {
        const int k0p = sp * D1KS;
#pragma unroll
        for (int j = 0; j < 4; j++)
            ra[j] = *(const uint4*)&A[(size_t)(rbase + 32 * j) * K1TOT + k0p + c8 * 8];
        loadB(0, rb);
    }
    for (int ch = 0; ch < D1KS / 64; ch++) {
#pragma unroll
        for (int j = 0; j < 4; j++) {
            int off = (rbase + 32 * j) * 72 + c8 * 8;
            *(uint4*)&sA[off] = ra[j];
            *(uint4*)&sB[off] = rb[j];
        }
        __syncthreads();
        if (ch + 1 < D1KS / 64) {
            const int k0p = sp * D1KS + (ch + 1) * 64;
#pragma unroll
            for (int j = 0; j < 4; j++)
                ra[j] = *(const uint4*)&A[(size_t)(rbase + 32 * j) * K1TOT + k0p + c8 * 8];
            loadB(ch + 1, rb);
        }
#pragma unroll
        for (int ks = 0; ks < 4; ks++) {
            uint32_t a[2][4], b[4][4];
            LDSM_X4(a[0], smem_u32(&sA[arow * 72 + ks * 16 + akoff]));
            LDSM_X4(a[1], smem_u32(&sA[(arow + 16) * 72 + ks * 16 + akoff]));
#pragma unroll
            for (int p = 0; p < 4; p++)
                LDSM_X4(b[p], smem_u32(&sB[(brow + p * 16) * 72 + ks * 16 + bkoff]));
#pragma unroll
            for (int mi = 0; mi < 2; mi++)
#pragma unroll
                for (int ni = 0; ni < 8; ni++)
                    MMA16816(acc[mi][ni], a[mi],
                             b[ni >> 1][(ni & 1) * 2], b[ni >> 1][(ni & 1) * 2 + 1]);
        }
        __syncthreads();
    }
    const int g = lane >> 2, tig = lane & 3;
#pragma unroll
    for (int mi = 0; mi < 2; mi++)
#pragma unroll
        for (int ni = 0; ni < 8; ni++)
#pragma unroll
            for (int e = 0; e < 4; e++) {
                int m = wm * 32 + mi * 16 + g + (e >> 1) * 8;
                int n = n0 + wn * 64 + ni * 8 + tig * 2 + (e & 1);
                PS[(size_t)(sp * 128 + m) * NPMAIN + n] = acc[mi][ni][e];
            }
}

// ---------------- SIMT conv for down2/down3 (tiny) ----------------
template<int CIN,int HIN,int WIN,int HOUT,int WOUT,int STRIDE,int SPLIT,int NPAD>
__global__ __launch_bounds__(256)
void dconv(const float* __restrict__ IN, const float* __restrict__ Wt,
           float* __restrict__ PART, int NIMG)
{
    constexpr int NCOL = HOUT * WOUT;
    constexpr int KTOT = 9 * CIN;
    constexpr int KS   = KTOT / SPLIT;
    const int sp = blockIdx.z;
    const int kbeg = sp * KS, kend = kbeg + KS;
    const int m0 = blockIdx.x * 64, n0 = blockIdx.y * 64;
    __shared__ float4 As4[8][16];
    __shared__ __align__(16) float Bs[8][64];
    float acc[4][4] = {};
    const int tid = threadIdx.x;
    const int tr = tid >> 4, tc = tid & 15;
    const int lr = (tid & 127) >> 4, lq = tid & 15;

    for (int k0 = kbeg; k0 < kend; k0 += 8) {
        if (tid < 128) {
            As4[lr][lq] = *reinterpret_cast<const float4*>(&Wt[(size_t)(k0 + lr) * 128 + m0 + lq * 4]);
        } else {
            int k = k0 + lr;
            int tap = k / CIN;
            int ci = k - tap * CIN;
            int ky = tap / 3 - 1, kx = tap - (tap / 3) * 3 - 1;
            const float* base = IN + (size_t)ci * (HIN * WIN);
#pragma unroll
            for (int e = 0; e < 4; e++) {
                int n = n0 + lq * 4 + e;
                int img = n / NCOL;
                int pos = n - img * NCOL;
                int oy = pos / WOUT, ox = pos - oy * WOUT;
                int iy = oy * STRIDE + ky, ix = ox * STRIDE + kx;
                float v = 0.f;
                if (img < NIMG && iy >= 0 && iy < HIN && ix >= 0 && ix < WIN)
                    v = __ldg(&base[(size_t)img * CIN * (HIN * WIN) + iy * WIN + ix]);
                Bs[lr][lq * 4 + e] = v;
            }
        }
        __syncthreads();
#pragma unroll
        for (int kk = 0; kk < 8; kk++) {
            float4 a = As4[kk][tr];
            float4 b = *reinterpret_cast<const float4*>(&Bs[kk][tc * 4]);
            acc[0][0] += a.x * b.x; acc[0][1] += a.x * b.y; acc[0][2] += a.x * b.z; acc[0][3] += a.x * b.w;
            acc[1][0] += a.y * b.x; acc[1][1] += a.y * b.y; acc[1][2] += a.y * b.z; acc[1][3] += a.y * b.w;
            acc[2][0] += a.z * b.x; acc[2][1] += a.z * b.y; acc[2][2] += a.z * b.z; acc[2][3] += a.z * b.w;
            acc[3][0] += a.w * b.x; acc[3][1] += a.w * b.y; acc[3][2] += a.w * b.z; acc[3][3] += a.w * b.w;
        }
        __syncthreads();
    }
#pragma unroll
    for (int i = 0; i < 4; i++) {
        int gm = m0 + tr * 4 + i;
#pragma unroll
        for (int j = 0; j < 4; j++) {
            int n = n0 + tc * 4 + j;
            PART[(size_t)(sp * 128 + gm) * NPAD + n] = acc[i][j];
        }
    }
}

// sum split-K partials + bias + relu -> [img][128][ncol]
__global__ void reduce_br(float* __restrict__ out, const float* __restrict__ part,
                          const float* __restrict__ bias, int nimg, int ncol,
                          int split, int npad)
{
    int idx = blockIdx.x * blockDim.x + threadIdx.x;
    int tot = nimg * 128 * ncol;
    if (idx >= tot) return;
    int img = idx / (128 * ncol);
    int r = idx - img * 128 * ncol;
    int m = r / ncol;
    int pos = r - m * ncol;
    int n = img * ncol + pos;
    float s = 0.f;
    for (int sp = 0; sp < split; sp++)
        s += part[(size_t)(sp * 128 + m) * npad + n];
    out[idx] = fmaxf(s + bias[m], 0.f);
}

// FC: one class per block, 8 rows per block
__global__ void fc8(const float* __restrict__ G, const float* __restrict__ W,
                    const float* __restrict__ bias, float* __restrict__ out, int K)
{
    int cls = blockIdx.x;
    int rb  = blockIdx.y;
    const float* g = G + (size_t)rb * 8 * K;
    const float* w = W + (size_t)cls * K;
    float acc[8] = {};
    for (int k = threadIdx.x; k < K; k += 256) {
        float wv = w[k];
#pragma unroll
        for (int r = 0; r < 8; r++) acc[r] += wv * g[(size_t)r * K + k];
    }
    __shared__ float sm[8][8];
    int lane = threadIdx.x & 31, wid = threadIdx.x >> 5;
#pragma unroll
    for (int r = 0; r < 8; r++) {
        float s = acc[r];
#pragma unroll
        for (int o = 16; o; o >>= 1) s += __shfl_xor_sync(0xffffffffu, s, o);
        if (lane == 0) sm[wid][r] = s;
    }
    __syncthreads();
    if (threadIdx.x < 8) {
        int r = threadIdx.x;
        float s = 0.f;
#pragma unroll
        for (int w2 = 0; w2 < 8; w2++) s += sm[w2][r];
        out[(rb * 8 + r) * CAT + cls] = s + bias[cls];
    }
}

__global__ void cin_k(const float* __restrict__ GP, const float* __restrict__ G8,
                      float* __restrict__ cin)
{
    int idx = blockIdx.x * blockDim.x + threadIdx.x;
    if (idx >= NB * 10240) return;
    int b = idx / 10240, k = idx - b * 10240;
    cin[idx] = (k < 8192) ? GP[(size_t)(b * 4 + (k >> 11)) * 2048 + (k & 2047)]
                          : G8[(size_t)b * 2048 + (k - 8192)];
}

// tidy 1x1 convs -> rpn scores
__global__ void rpn_k(const float* __restrict__ d1, const float* __restrict__ d2,
                      const float* __restrict__ d3,
                      const float* __restrict__ w1, const float* __restrict__ b1,
                      const float* __restrict__ w2, const float* __restrict__ b2,
                      const float* __restrict__ w3, const float* __restrict__ b3,
                      float* __restrict__ rpn)
{
    int img = blockIdx.x;
    int j = blockIdx.y * blockDim.x + threadIdx.x;
    if (j >= NANCH) return;
    float s;
    if (j < 1176) {
        int ch = j / 196, pos = j % 196;
        const float* in = d1 + (size_t)img * 128 * 196 + pos;
        const float* w  = w1 + ch * 128;
        s = b1[ch];
        for (int c = 0; c < 128; c++) s += in[c * 196] * w[c];
    } else if (j < 1470) {
        int jj = j - 1176;
        int ch = jj / 49, pos = jj % 49;
        const float* in = d2 + (size_t)img * 128 * 49 + pos;
        const float* w  = w2 + ch * 128;
        s = b2[ch];
        for (int c = 0; c < 128; c++) s += in[c * 49] * w[c];
    } else {
        int jj = j - 1470;
        int ch = jj / 16, pos = jj % 16;
        const float* in = d3 + (size_t)img * 128 * 16 + pos;
        const float* w  = w3 + ch * 128;
        s = b3[ch];
        for (int c = 0; c < 128; c++) s += in[c * 16] * w[c];
    }
    rpn[img * NANCH + j] = s;
}

// NMS (first-index argmax tie-break)
__global__ void nms_k(const float* __restrict__ rpn,
                      float* __restrict__ out_idx_f, float* __restrict__ out_prob)
{
    int img = blockIdx.x;
    __shared__ float sc[NANCH];
    __shared__ unsigned char valid[NANCH];
    __shared__ float rv[256];
    __shared__ int   ri[256];
    __shared__ float pb[5];
    int tid = threadIdx.x;
    for (int j = tid; j < NANCH; j += 256) {
        sc[j] = rpn[img * NANCH + j];
        valid[j] = 1;
    }
    __syncthreads();
    for (int t = 0; t < 4; t++) {
        float bvv = -INFINITY;
        int   bi = 0x7fffffff;
        for (int j = tid; j < NANCH; j += 256) {
            if (valid[j]) {
                float v = sc[j];
                if (v > bvv || (v == bvv && j < bi)) { bvv = v; bi = j; }
            }
        }
        rv[tid] = bvv; ri[tid] = bi;
        __syncthreads();
        for (int o = 128; o; o >>= 1) {
            if (tid < o) {
                float v2 = rv[tid + o]; int i2 = ri[tid + o];
                if (v2 > rv[tid] || (v2 == rv[tid] && i2 < ri[tid])) { rv[tid] = v2; ri[tid] = i2; }
            }
            __syncthreads();
        }
        if (tid == 0) {
            int p = ri[0];
            g_topidx[img * 4 + t] = p;
            out_idx_f[img * 4 + t] = (float)p;
            out_prob [img * 4 + t] = sc[p];
            pb[0] = (float)g_boxes[p * 4 + 0];
            pb[1] = (float)g_boxes[p * 4 + 1];
            pb[2] = (float)g_boxes[p * 4 + 2];
            pb[3] = (float)g_boxes[p * 4 + 3];
            pb[4] = g_area[p];
        }
        __syncthreads();
        float by0 = pb[0], bx0 = pb[1], by1 = pb[2], bx1 = pb[3], ba = pb[4];
        for (int j = tid; j < NANCH; j += 256) {
            if (!valid[j]) continue;
            float ty = fmaxf((float)g_boxes[j * 4 + 0], by0);
            float tx = fmaxf((float)g_boxes[j * 4 + 1], bx0);
            float cy = fminf((float)g_boxes[j * 4 + 2], by1);
            float cx = fminf((float)g_boxes[j * 4 + 3], bx1);
            float wh0 = cy - ty, wh1 = cx - tx;
            float inter = (wh0 < 0.f || wh1 < 0.f) ? 0.f : wh0 * wh1;
            float iou = inter / (g_area[j] + ba - inter);
            if (!(iou < 0.25f)) valid[j] = 0;
        }
        __syncthreads();
    }
}

// ---------------- launch ----------------
extern "C" void kernel_launch(void* const* d_in, const int* in_sizes, int n_in,
                              void* d_out, int out_size)
{
    const float* x     = (const float*)d_in[0];
    const float* stemw = (const float*)d_in[1];
    const float* stemb = (const float*)d_in[2];
    const float* fcw   = (const float*)d_in[3];
    const float* fcb   = (const float*)d_in[4];
    const float* d1w   = (const float*)d_in[5];
    const float* d1b   = (const float*)d_in[6];
    const float* d2w   = (const float*)d_in[7];
    const float* d2b   = (const float*)d_in[8];
    const float* d3w   = (const float*)d_in[9];
    const float* d3b   = (const float*)d_in[10];
    const float* t1w   = (const float*)d_in[11];
    const float* t1b   = (const float*)d_in[12];
    const float* t2w   = (const float*)d_in[13];
    const float* t2b   = (const float*)d_in[14];
    const float* t3w   = (const float*)d_in[15];
    const float* t3b   = (const float*)d_in[16];
    const float* cw    = (const float*)d_in[17];
    const float* cb    = (const float*)d_in[18];
    const float* pw    = (const float*)d_in[19];
    const float* pb    = (const float*)d_in[20];
    float* out = (float*)d_out;

    float *WT2, *WT3, *PS, *D1, *D2, *D3, *G8, *GP, *CIN_, *RPN;
    __nv_bfloat16 *WS, *BC, *W1, *FTH, *FTL;
    cudaGetSymbolAddress((void**)&WS,  g_Ws);
    cudaGetSymbolAddress((void**)&BC,  g_bc);
    cudaGetSymbolAddress((void**)&W1,  g_W1);
    cudaGetSymbolAddress((void**)&FTH, g_Fthi);
    cudaGetSymbolAddress((void**)&FTL, g_Ftlo);
    cudaGetSymbolAddress((void**)&WT2, g_wt2);
    cudaGetSymbolAddress((void**)&WT3, g_wt3);
    cudaGetSymbolAddress((void**)&PS,  g_ps);
    cudaGetSymbolAddress((void**)&D1,  g_d1);
    cudaGetSymbolAddress((void**)&D2,  g_d2);
    cudaGetSymbolAddress((void**)&D3,  g_d3);
    cudaGetSymbolAddress((void**)&G8,  g_g8);
    cudaGetSymbolAddress((void**)&GP,  g_gp);
    cudaGetSymbolAddress((void**)&CIN_, g_cin);
    cudaGetSymbolAddress((void**)&RPN, g_rpn);

    zero_k<<<(NPART * 2048 + 255) / 256, 256>>>(G8, GP);
    boxes_k<<<7, 256>>>();
    split_stemw<<<(2048 * KS3 + 255) / 256, 256>>>(stemw, WS);
    split_dw1<<<(128 * K1TOT + 255) / 256, 256>>>(d1w, W1);
    im2col_bf16<<<(NPMAIN * KSEG + 255) / 256, 256>>>(x, BC, NMAIN, NPMAIN);

    // main stem: fused GEMM + pooled G8 + transposed bf16 feature planes
    mma_stem<1><<<dim3(16, 13), 256>>>(WS, BC, stemb, G8, FTH, FTL, NMAIN, NB);

    // down tower
    mma_down1<<<dim3(13, D1SPLIT), 256>>>(W1, FTH, FTL, PS);
    reduce_br<<<(NB * 128 * 196 + 255) / 256, 256>>>(D1, PS, d1b, NB, 196, D1SPLIT, NPMAIN);

    tr_dw<128><<<(1152 * 128 + 255) / 256, 256>>>(d2w, WT2);
    tr_dw<128><<<(1152 * 128 + 255) / 256, 256>>>(d3w, WT3);
    dconv<128,14,14,7,7,2,8,448><<<dim3(2, 7, 8), 256>>>(D1, WT2, PS, NB);
    reduce_br<<<(NB * 128 * 49 + 255) / 256, 256>>>(D2, PS, d2b, NB, 49, 8, 448);
    dconv<128,7,7,4,4,2,8,128><<<dim3(2, 2, 8), 256>>>(D2, WT3, PS, NB);
    reduce_br<<<(NB * 128 * 16 + 255) / 256, 256>>>(D3, PS, d3b, NB, 16, 8, 128);

    fc8<<<dim3(CAT, 1), 256>>>(G8, fcw, fcb, out, 2048);

    rpn_k<<<dim3(NB, 7), 256>>>(D1, D2, D3, t1w, t1b, t2w, t2b, t3w, t3b, RPN);
    nms_k<<<NB, 256>>>(RPN, out + 9600, out + 9632);

    // part stem: fused crop+im2col, then fused GEMM + pooled GP (no Fp buffer)
    part_bcol<<<(NPART_N * KSEG + 255) / 256, 256>>>(x, BC);
    mma_stem<0><<<dim3(16, 49), 256>>>(WS, BC, stemb, GP, nullptr, nullptr, NPART_N, NPART);

    // heads
    fc8<<<dim3(CAT, 4), 256>>>(GP, pw, pb, out + 3200, 2048);
    cin_k<<<(NB * 10240 + 255) / 256, 256>>>(GP, G8, CIN_);
    fc8<<<dim3(CAT, 1), 256>>>(CIN_, cw, cb, out + 1600, 10240);

    (void)in_sizes; (void)n_in; (void)out_size;
}